// round 12
// baseline (speedup 1.0000x reference)
#include <cuda_runtime.h>
#include <cuda_bf16.h>
#include <math.h>
#include <stdint.h>

// Problem constants
#define B_    16
#define C_    256
#define NTOK  16384
#define NPOS  1024
#define HEADS 8
#define DHEAD 32
#define HID   1024
#define LOG2E 1.4426950408889634f

// ---------------------------------------------------------------------------
// Scratch layout (float units)
// ---------------------------------------------------------------------------
#define OFF_WB     0u
#define WB_QKV     0u
#define WB_PROJ    196608u
#define WB_W1      262144u
#define WB_W2      524288u
#define WB_TOTAL   786432u

#define OFF_X1B    524288u
#define OFF_QKVB   2621440u
#define OFF_BIAS8  8912896u
#define OFF_ATTNB  13107200u
#define OFF_X3     15204352u
#define OFF_X4B    19398656u
#define OFF_H1B    21495808u
#define SCRATCH_FLOATS 33554432u

__device__ float g_scratch[SCRATCH_FLOATS];

// ---------------------------------------------------------------------------
// Weight fp32 -> bf16
// ---------------------------------------------------------------------------
__global__ __launch_bounds__(256)
void convert_w_kernel(const float* __restrict__ a, const float* __restrict__ b,
                      const float* __restrict__ c, const float* __restrict__ d,
                      __nv_bfloat16* __restrict__ out)
{
    unsigned i = blockIdx.x * 256u + threadIdx.x;
    if (i < WB_PROJ)            out[i] = __float2bfloat16(a[i]);
    else if (i < WB_W1)         out[i] = __float2bfloat16(b[i - WB_PROJ]);
    else if (i < WB_W2)         out[i] = __float2bfloat16(c[i - WB_W1]);
    else if (i < WB_TOTAL)      out[i] = __float2bfloat16(d[i - WB_W2]);
}

// ---------------------------------------------------------------------------
// Relative-position bias precompute (pre-scaled by log2e)
// ---------------------------------------------------------------------------
__global__ __launch_bounds__(256)
void bias_pre(const float* __restrict__ table, const int* __restrict__ ridx,
              __nv_bfloat16* __restrict__ bias8)
{
    unsigned id = blockIdx.x * 256u + threadIdx.x;
    int idx = ridx[id];
    const float* tr = table + (size_t)idx * HEADS;
    #pragma unroll
    for (int h = 0; h < HEADS; h++)
        bias8[(size_t)h * 1048576u + id] = __float2bfloat16(tr[h] * LOG2E);
}

// ---------------------------------------------------------------------------
// LN1: fused transpose LayerNorm (B,C,n) fp32 -> token-major bf16
// ---------------------------------------------------------------------------
__global__ __launch_bounds__(256)
void ln1_kernel(const float* __restrict__ in, const float* __restrict__ w,
                const float* __restrict__ bv, __nv_bfloat16* __restrict__ out)
{
    __shared__ float tile[C_][33];
    __shared__ float red1[8][32], red2[8][32];
    __shared__ float smu[32], srs[32];

    const int bb = blockIdx.y, p0 = blockIdx.x * 32;
    const int tid = threadIdx.x;

    #pragma unroll
    for (int it = 0; it < 32; it++) {
        int id = it * 256 + tid;
        int c = id >> 5, pp = id & 31;
        tile[c][pp] = in[((size_t)(bb * C_ + c)) * NPOS + p0 + pp];
    }
    __syncthreads();

    {
        int token = tid & 31, part = tid >> 5;
        float s1 = 0.f, s2 = 0.f;
        #pragma unroll
        for (int cc = 0; cc < 32; cc++) {
            float v = tile[part * 32 + cc][token];
            s1 += v; s2 += v * v;
        }
        red1[part][token] = s1;
        red2[part][token] = s2;
    }
    __syncthreads();
    if (tid < 32) {
        float t1 = 0.f, t2 = 0.f;
        #pragma unroll
        for (int p = 0; p < 8; p++) { t1 += red1[p][tid]; t2 += red2[p][tid]; }
        float mu  = t1 * (1.f / C_);
        float var = t2 * (1.f / C_) - mu * mu;
        smu[tid] = mu;
        srs[tid] = rsqrtf(var + 1e-5f);
    }
    __syncthreads();

    const float wc = w[tid], bc = bv[tid];
    #pragma unroll
    for (int it = 0; it < 32; it++) {
        float v = tile[tid][it];
        out[((size_t)(bb * NPOS + p0 + it)) * C_ + tid] =
            __float2bfloat16((v - smu[it]) * srs[it] * wc + bc);
    }
}

// ---------------------------------------------------------------------------
// bf16 mma.sync GEMM (128 thr / 4 warps, warp tile 64x64) — EPI 0/2/3
// ---------------------------------------------------------------------------
#define AKP 40
#define BNP 136

#define MMA16816(acc, af, b0, b1)                                              \
    asm volatile("mma.sync.aligned.m16n8k16.row.col.f32.bf16.bf16.f32 "        \
                 "{%0,%1,%2,%3}, {%4,%5,%6,%7}, {%8,%9}, {%0,%1,%2,%3};"       \
                 : "+f"(acc[0]), "+f"(acc[1]), "+f"(acc[2]), "+f"(acc[3])      \
                 : "r"(af[0]), "r"(af[1]), "r"(af[2]), "r"(af[3]),             \
                   "r"(b0), "r"(b1))

template<int EPI>
__global__ __launch_bounds__(128)
void mma_gemm(const __nv_bfloat16* __restrict__ A, const __nv_bfloat16* __restrict__ Bw,
              int M, int N, int K,
              const float* __restrict__ bias, const float* __restrict__ res,
              float* __restrict__ outf, __nv_bfloat16* __restrict__ outb)
{
    __shared__ __align__(16) __nv_bfloat16 As[3][128][AKP];
    __shared__ __align__(16) __nv_bfloat16 Bs[3][32][BNP];

    const int tid = threadIdx.x, lane = tid & 31, wid = tid >> 5;
    const int wm = wid >> 1, wn = wid & 1;
    const int m0 = blockIdx.y * 128, n0 = blockIdx.x * 128;

    float acc[4][8][4] = {};
    const int S = K >> 5;

    auto loadStage = [&](int s, int buf) {
        int kpos = s << 5;
        #pragma unroll
        for (int j = 0; j < 4; j++) {
            int id = tid + j * 128;
            int r = id >> 2, kc = id & 3;
            const __nv_bfloat16* g = A + (size_t)(m0 + r) * K + kpos + kc * 8;
            unsigned dst = (unsigned)__cvta_generic_to_shared(&As[buf][r][kc * 8]);
            asm volatile("cp.async.cg.shared.global [%0], [%1], 16;\n"
                         :: "r"(dst), "l"(g));
        }
        #pragma unroll
        for (int j = 0; j < 4; j++) {
            int id = tid + j * 128;
            int r = id >> 4, nc = id & 15;
            const __nv_bfloat16* g = Bw + (size_t)(kpos + r) * N + n0 + nc * 8;
            unsigned dst = (unsigned)__cvta_generic_to_shared(&Bs[buf][r][nc * 8]);
            asm volatile("cp.async.cg.shared.global [%0], [%1], 16;\n"
                         :: "r"(dst), "l"(g));
        }
        asm volatile("cp.async.commit_group;\n" ::: "memory");
    };

    loadStage(0, 0);
    loadStage(1, 1);

    int buf = 0;
    for (int s = 0; s < S; s++) {
        asm volatile("cp.async.wait_group 1;\n" ::: "memory");
        __syncthreads();
        if (s + 2 < S) {
            int nb = buf + 2; if (nb >= 3) nb -= 3;
            loadStage(s + 2, nb);
        }

        #pragma unroll
        for (int ks = 0; ks < 2; ks++) {
            const int kb = ks * 16;
            unsigned afr[4][4];
            #pragma unroll
            for (int mt = 0; mt < 4; mt++) {
                unsigned ad = (unsigned)__cvta_generic_to_shared(
                    &As[buf][wm * 64 + mt * 16 + (lane & 15)][kb + (lane >> 4) * 8]);
                asm volatile("ldmatrix.sync.aligned.m8n8.x4.shared.b16 {%0,%1,%2,%3}, [%4];"
                             : "=r"(afr[mt][0]), "=r"(afr[mt][1]),
                               "=r"(afr[mt][2]), "=r"(afr[mt][3]) : "r"(ad));
            }
            unsigned bfr[8][2];
            #pragma unroll
            for (int np = 0; np < 4; np++) {
                int quad = lane >> 3, rr = lane & 7;
                int row = kb + (quad & 1) * 8 + rr;
                int col = wn * 64 + np * 16 + (quad >> 1) * 8;
                unsigned bd = (unsigned)__cvta_generic_to_shared(&Bs[buf][row][col]);
                asm volatile("ldmatrix.sync.aligned.m8n8.x4.trans.shared.b16 {%0,%1,%2,%3}, [%4];"
                             : "=r"(bfr[np * 2][0]), "=r"(bfr[np * 2][1]),
                               "=r"(bfr[np * 2 + 1][0]), "=r"(bfr[np * 2 + 1][1]) : "r"(bd));
            }
            #pragma unroll
            for (int mt = 0; mt < 4; mt++)
                #pragma unroll
                for (int nt = 0; nt < 8; nt++)
                    MMA16816(acc[mt][nt], afr[mt], bfr[nt][0], bfr[nt][1]);
        }
        buf++; if (buf >= 3) buf = 0;
    }

    const int lr = lane >> 2, lc = (lane & 3) * 2;
    #pragma unroll
    for (int mt = 0; mt < 4; mt++) {
        #pragma unroll
        for (int half = 0; half < 2; half++) {
            int mrow = m0 + wm * 64 + mt * 16 + lr + half * 8;
            int bb = mrow >> 10, p = mrow & 1023;
            #pragma unroll
            for (int nt = 0; nt < 8; nt++) {
                if (EPI == 0) {
                    int c = n0 + wn * 64 + nt * 8 + lc;
                    int part = c >> 8, hh = (c >> 5) & 7, d = c & 31;
                    __nv_bfloat162 pr = __floats2bfloat162_rn(
                        acc[mt][nt][half * 2 + 0], acc[mt][nt][half * 2 + 1]);
                    *(__nv_bfloat162*)&outb[(size_t)part * 4194304u +
                        (((size_t)(bb * HEADS + hh)) * NPOS + p) * DHEAD + d] = pr;
                } else {
                    #pragma unroll
                    for (int e = 0; e < 2; e++) {
                        int c = n0 + wn * 64 + nt * 8 + lc + e;
                        float v = acc[mt][nt][half * 2 + e];
                        if (EPI == 2) {
                            float t = v + bias[c];
                            outb[(size_t)mrow * N + c] = __float2bfloat16(
                                0.5f * t * (1.f + erff(t * 0.70710678118654752f)));
                        } else {
                            outf[((size_t)(bb * C_ + c)) * NPOS + p] =
                                v + bias[c] + res[(size_t)mrow * C_ + c];
                        }
                    }
                }
            }
        }
    }
}

// ---------------------------------------------------------------------------
// Fused proj GEMM + bias + residual + LayerNorm2 (unchanged from R10)
// ---------------------------------------------------------------------------
#define PBNP 264
#define PA_STG (128 * AKP)
#define PB_STG (32 * PBNP)
#define PSMEM_BYTES ((3 * PA_STG + 3 * PB_STG) * 2)

__global__ __launch_bounds__(256)
void proj_ln_kernel(const __nv_bfloat16* __restrict__ A, const __nv_bfloat16* __restrict__ Bw,
                    const float* __restrict__ bias, const float* __restrict__ res,
                    const float* __restrict__ n2w, const float* __restrict__ n2b,
                    float* __restrict__ x3, __nv_bfloat16* __restrict__ x4b)
{
    extern __shared__ __align__(16) __nv_bfloat16 dsm[];
    __nv_bfloat16* AsBase = dsm;
    __nv_bfloat16* BsBase = dsm + 3 * PA_STG;
    __shared__ float sum4[4][128], sq4[4][128];
    __shared__ float smu[128], srs[128];

    const int tid = threadIdx.x, lane = tid & 31, wid = tid >> 5;
    const int wm = wid >> 2, wn = wid & 3;
    const int m0 = blockIdx.x * 128;
    const int K = C_, N = C_;

    float acc[4][8][4] = {};

    auto loadStage = [&](int s, int buf) {
        int kpos = s << 5;
        __nv_bfloat16* As = AsBase + buf * PA_STG;
        __nv_bfloat16* Bs = BsBase + buf * PB_STG;
        #pragma unroll
        for (int j = 0; j < 2; j++) {
            int id = tid + j * 256;
            int r = id >> 2, kc = id & 3;
            const __nv_bfloat16* g = A + (size_t)(m0 + r) * K + kpos + kc * 8;
            unsigned dst = (unsigned)__cvta_generic_to_shared(As + r * AKP + kc * 8);
            asm volatile("cp.async.cg.shared.global [%0], [%1], 16;\n" :: "r"(dst), "l"(g));
        }
        #pragma unroll
        for (int j = 0; j < 4; j++) {
            int id = tid + j * 256;
            int r = id >> 5, nc = id & 31;
            const __nv_bfloat16* g = Bw + (size_t)(kpos + r) * N + nc * 8;
            unsigned dst = (unsigned)__cvta_generic_to_shared(Bs + r * PBNP + nc * 8);
            asm volatile("cp.async.cg.shared.global [%0], [%1], 16;\n" :: "r"(dst), "l"(g));
        }
        asm volatile("cp.async.commit_group;\n" ::: "memory");
    };

    loadStage(0, 0);
    loadStage(1, 1);

    int buf = 0;
    const int S = K >> 5;
    for (int s = 0; s < S; s++) {
        asm volatile("cp.async.wait_group 1;\n" ::: "memory");
        __syncthreads();
        if (s + 2 < S) {
            int nb = buf + 2; if (nb >= 3) nb -= 3;
            loadStage(s + 2, nb);
        }
        __nv_bfloat16* As = AsBase + buf * PA_STG;
        __nv_bfloat16* Bs = BsBase + buf * PB_STG;

        #pragma unroll
        for (int ks = 0; ks < 2; ks++) {
            const int kb = ks * 16;
            unsigned afr[4][4];
            #pragma unroll
            for (int mt = 0; mt < 4; mt++) {
                unsigned ad = (unsigned)__cvta_generic_to_shared(
                    As + (wm * 64 + mt * 16 + (lane & 15)) * AKP + kb + (lane >> 4) * 8);
                asm volatile("ldmatrix.sync.aligned.m8n8.x4.shared.b16 {%0,%1,%2,%3}, [%4];"
                             : "=r"(afr[mt][0]), "=r"(afr[mt][1]),
                               "=r"(afr[mt][2]), "=r"(afr[mt][3]) : "r"(ad));
            }
            unsigned bfr[8][2];
            #pragma unroll
            for (int np = 0; np < 4; np++) {
                int quad = lane >> 3, rr = lane & 7;
                int row = kb + (quad & 1) * 8 + rr;
                int col = wn * 64 + np * 16 + (quad >> 1) * 8;
                unsigned bd = (unsigned)__cvta_generic_to_shared(Bs + row * PBNP + col);
                asm volatile("ldmatrix.sync.aligned.m8n8.x4.trans.shared.b16 {%0,%1,%2,%3}, [%4];"
                             : "=r"(bfr[np * 2][0]), "=r"(bfr[np * 2][1]),
                               "=r"(bfr[np * 2 + 1][0]), "=r"(bfr[np * 2 + 1][1]) : "r"(bd));
            }
            #pragma unroll
            for (int mt = 0; mt < 4; mt++)
                #pragma unroll
                for (int nt = 0; nt < 8; nt++)
                    MMA16816(acc[mt][nt], afr[mt], bfr[nt][0], bfr[nt][1]);
        }
        buf++; if (buf >= 3) buf = 0;
    }

    const int lr = lane >> 2, lc = (lane & 3) * 2;

    #pragma unroll
    for (int mt = 0; mt < 4; mt++) {
        #pragma unroll
        for (int half = 0; half < 2; half++) {
            int mrow = m0 + wm * 64 + mt * 16 + lr + half * 8;
            int bb = mrow >> 10, p = mrow & 1023;
            float s1 = 0.f, s2 = 0.f;
            #pragma unroll
            for (int nt = 0; nt < 8; nt++) {
                #pragma unroll
                for (int e = 0; e < 2; e++) {
                    int c = wn * 64 + nt * 8 + lc + e;
                    float t = acc[mt][nt][half * 2 + e] + bias[c] +
                              res[((size_t)(bb * C_ + c)) * NPOS + p];
                    acc[mt][nt][half * 2 + e] = t;
                    s1 += t; s2 += t * t;
                }
            }
            s1 += __shfl_xor_sync(0xffffffffu, s1, 1);
            s2 += __shfl_xor_sync(0xffffffffu, s2, 1);
            s1 += __shfl_xor_sync(0xffffffffu, s1, 2);
            s2 += __shfl_xor_sync(0xffffffffu, s2, 2);
            if ((lane & 3) == 0) {
                int r = wm * 64 + mt * 16 + lr + half * 8;
                sum4[wn][r] = s1;
                sq4[wn][r] = s2;
            }
        }
    }
    __syncthreads();
    if (tid < 128) {
        float t1 = sum4[0][tid] + sum4[1][tid] + sum4[2][tid] + sum4[3][tid];
        float t2 = sq4[0][tid] + sq4[1][tid] + sq4[2][tid] + sq4[3][tid];
        float mu  = t1 * (1.f / C_);
        float var = t2 * (1.f / C_) - mu * mu;
        smu[tid] = mu;
        srs[tid] = rsqrtf(var + 1e-5f);
    }
    __syncthreads();

    #pragma unroll
    for (int mt = 0; mt < 4; mt++) {
        #pragma unroll
        for (int half = 0; half < 2; half++) {
            int r = wm * 64 + mt * 16 + lr + half * 8;
            int mrow = m0 + r;
            float mu = smu[r], rs = srs[r];
            #pragma unroll
            for (int nt = 0; nt < 8; nt++) {
                int c = wn * 64 + nt * 8 + lc;
                float t0 = acc[mt][nt][half * 2 + 0];
                float t1v = acc[mt][nt][half * 2 + 1];
                *(float2*)&x3[(size_t)mrow * C_ + c] = make_float2(t0, t1v);
                float g0 = (t0 - mu) * rs * n2w[c] + n2b[c];
                float g1 = (t1v - mu) * rs * n2w[c + 1] + n2b[c + 1];
                __nv_bfloat162 pr = __floats2bfloat162_rn(g0, g1);
                *(__nv_bfloat162*)&x4b[(size_t)mrow * C_ + c] = pr;
            }
        }
    }
}

// ---------------------------------------------------------------------------
// Attention helpers (device inline; operate on register arrays by reference)
// ---------------------------------------------------------------------------
__device__ __forceinline__ void attn_computeS(
    float (&sacc)[8][4], const __nv_bfloat16 (*Ksb)[40],
    const unsigned (&qf)[2][4], int lane)
{
    #pragma unroll
    for (int nt = 0; nt < 8; nt++)
        #pragma unroll
        for (int e = 0; e < 4; e++) sacc[nt][e] = 0.f;
    #pragma unroll
    for (int kk = 0; kk < 2; kk++) {
        unsigned bfr[8][2];
        #pragma unroll
        for (int np = 0; np < 4; np++) {
            int g = lane >> 3;
            unsigned ad = (unsigned)__cvta_generic_to_shared(
                &Ksb[(np * 2 + (g >> 1)) * 8 + (lane & 7)][kk * 16 + (g & 1) * 8]);
            asm volatile("ldmatrix.sync.aligned.m8n8.x4.shared.b16 {%0,%1,%2,%3}, [%4];"
                         : "=r"(bfr[np * 2][0]), "=r"(bfr[np * 2][1]),
                           "=r"(bfr[np * 2 + 1][0]), "=r"(bfr[np * 2 + 1][1]) : "r"(ad));
        }
        #pragma unroll
        for (int nt = 0; nt < 8; nt++)
            MMA16816(sacc[nt], qf[kk], bfr[nt][0], bfr[nt][1]);
    }
}

__device__ __forceinline__ void attn_softmax_pv(
    float (&sacc)[8][4], float (&oacc)[4][4], float (&lp)[2],
    const __nv_bfloat16* __restrict__ bprow0,   // bias row base for half 0
    const __nv_bfloat16 (*Vsb)[40],
    int lane, __nv_bfloat162 k2)
{
    const int lc = (lane & 3) * 2;
    unsigned pfr[8][2];
    #pragma unroll
    for (int half = 0; half < 2; half++) {
        const __nv_bfloat16* brow = bprow0 + (size_t)(half * 8) * NPOS;
        float rsum = 0.f;
        #pragma unroll
        for (int nt = 0; nt < 8; nt++) {
            unsigned bb2 = *(const unsigned*)(brow + nt * 8 + lc);
            __nv_bfloat162 bbv = *reinterpret_cast<__nv_bfloat162*>(&bb2);
            __nv_bfloat162 s2 = __floats2bfloat162_rn(
                sacc[nt][half * 2 + 0], sacc[nt][half * 2 + 1]);
            __nv_bfloat162 arg = __hfma2(s2, k2, bbv);
            unsigned argr = *reinterpret_cast<unsigned*>(&arg);
            unsigned p2r;
            asm("ex2.approx.ftz.bf16x2 %0, %1;" : "=r"(p2r) : "r"(argr));
            pfr[nt][half] = p2r;
            float2 pf2 = __bfloat1622float2(*reinterpret_cast<__nv_bfloat162*>(&p2r));
            rsum += pf2.x + pf2.y;
        }
        lp[half] += rsum;
    }
    #pragma unroll
    for (int kc = 0; kc < 4; kc++) {
        unsigned pf[4];
        pf[0] = pfr[2 * kc][0];
        pf[1] = pfr[2 * kc][1];
        pf[2] = pfr[2 * kc + 1][0];
        pf[3] = pfr[2 * kc + 1][1];

        unsigned bv[4][2];
        #pragma unroll
        for (int np = 0; np < 2; np++) {
            int quad = lane >> 3, rr = lane & 7;
            unsigned ad = (unsigned)__cvta_generic_to_shared(
                &Vsb[kc * 16 + (quad & 1) * 8 + rr][np * 16 + (quad >> 1) * 8]);
            asm volatile("ldmatrix.sync.aligned.m8n8.x4.trans.shared.b16 {%0,%1,%2,%3}, [%4];"
                         : "=r"(bv[np * 2][0]), "=r"(bv[np * 2][1]),
                           "=r"(bv[np * 2 + 1][0]), "=r"(bv[np * 2 + 1][1]) : "r"(ad));
        }
        #pragma unroll
        for (int nv = 0; nv < 4; nv++)
            MMA16816(oacc[nv], pf, bv[nv][0], bv[nv][1]);
    }
}

// ---------------------------------------------------------------------------
// Tensor-core flash attention — Q-tile 64, 128 thr / 4 warps, 3 CTAs/SM.
// Cross-tile software pipeline: S(t+1) issued BEFORE softmax(t)/PV(t) so the
// tensor pipe executes next-tile S while this warp does MUFU/ALU softmax.
// ---------------------------------------------------------------------------
__global__ __launch_bounds__(128, 3)
void attn_mma(const __nv_bfloat16* __restrict__ qkv,
              const __nv_bfloat16* __restrict__ bias8,
              __nv_bfloat16* __restrict__ out)
{
    __shared__ __align__(16) __nv_bfloat16 Qs[64][40];
    __shared__ __align__(16) __nv_bfloat16 Ks[3][64][40];
    __shared__ __align__(16) __nv_bfloat16 Vs[3][64][40];

    const int tid = threadIdx.x, lane = tid & 31, w = tid >> 5;
    const int qt = blockIdx.x, h = blockIdx.y, b = blockIdx.z;
    const int i0 = qt * 64;
    const size_t headBase = ((size_t)(b * HEADS + h)) * NPOS * DHEAD;
    const __nv_bfloat16* qg = qkv + headBase;
    const __nv_bfloat16* kg = qkv + 4194304u + headBase;
    const __nv_bfloat16* vg = qkv + 8388608u + headBase;

    // Q tile (64 rows) -> smem (group 0)
    {
        int id = tid;
        #pragma unroll
        for (int it = 0; it < 2; it++, id += 128) {
            int r = id >> 2, kc = id & 3;
            const __nv_bfloat16* g = qg + (size_t)(i0 + r) * DHEAD + kc * 8;
            unsigned dst = (unsigned)__cvta_generic_to_shared(&Qs[r][kc * 8]);
            asm volatile("cp.async.cg.shared.global [%0], [%1], 16;\n" :: "r"(dst), "l"(g));
        }
        asm volatile("cp.async.commit_group;\n" ::: "memory");
    }

    auto loadKV = [&](int t, int buf) {
        int j0 = t * 64;
        #pragma unroll
        for (int it = 0; it < 2; it++) {
            int id = tid + it * 128;
            int r = id >> 2, kc = id & 3;
            const __nv_bfloat16* gk = kg + (size_t)(j0 + r) * DHEAD + kc * 8;
            unsigned dk = (unsigned)__cvta_generic_to_shared(&Ks[buf][r][kc * 8]);
            asm volatile("cp.async.cg.shared.global [%0], [%1], 16;\n" :: "r"(dk), "l"(gk));
            const __nv_bfloat16* gv = vg + (size_t)(j0 + r) * DHEAD + kc * 8;
            unsigned dv = (unsigned)__cvta_generic_to_shared(&Vs[buf][r][kc * 8]);
            asm volatile("cp.async.cg.shared.global [%0], [%1], 16;\n" :: "r"(dv), "l"(gv));
        }
        asm volatile("cp.async.commit_group;\n" ::: "memory");
    };

    loadKV(0, 0);      // group 1
    loadKV(1, 1);      // group 2

    unsigned qf[2][4];
    float oacc[4][4] = {};
    float lp[2] = {0.f, 0.f};
    const int lr = lane >> 2;
    const float k1 = 0.17677669529663687f * LOG2E;
    const __nv_bfloat162 k2 = __float2bfloat162_rn(k1);
    const __nv_bfloat16* bprow_base =
        bias8 + ((size_t)h << 20) + (size_t)(i0 + w * 16 + lr) * NPOS;

    // Prologue: wait Q + KV0 (allow KV1 pending), load Q frags, S(0)
    asm volatile("cp.async.wait_group 1;\n" ::: "memory");
    __syncthreads();
    #pragma unroll
    for (int kk = 0; kk < 2; kk++) {
        unsigned ad = (unsigned)__cvta_generic_to_shared(
            &Qs[w * 16 + (lane & 15)][kk * 16 + (lane >> 4) * 8]);
        asm volatile("ldmatrix.sync.aligned.m8n8.x4.shared.b16 {%0,%1,%2,%3}, [%4];"
                     : "=r"(qf[kk][0]), "=r"(qf[kk][1]),
                       "=r"(qf[kk][2]), "=r"(qf[kk][3]) : "r"(ad));
    }
    float saccA[8][4], saccB[8][4];
    attn_computeS(saccA, Ks[0], qf, lane);

    // Pipelined main loop: unroll by 2 to ping-pong saccA/saccB
    #pragma unroll
    for (int tt = 0; tt < 16; tt += 2) {
        // step t = tt  (cur = A, next = B)
        {
            const int t = tt;
            if (t + 1 < 16) {
                asm volatile("cp.async.wait_group 0;\n" ::: "memory");
                __syncthreads();
                if (t + 2 < 16) loadKV(t + 2, (t + 2) % 3);
                attn_computeS(saccB, Ks[(t + 1) % 3], qf, lane);
            }
            attn_softmax_pv(saccA, oacc, lp, bprow_base + t * 64, Vs[t % 3], lane, k2);
        }
        // step t = tt+1  (cur = B, next = A)
        {
            const int t = tt + 1;
            if (t + 1 < 16) {
                asm volatile("cp.async.wait_group 0;\n" ::: "memory");
                __syncthreads();
                if (t + 2 < 16) loadKV(t + 2, (t + 2) % 3);
                attn_computeS(saccA, Ks[(t + 1) % 3], qf, lane);
            }
            attn_softmax_pv(saccB, oacc, lp, bprow_base + t * 64, Vs[t % 3], lane, k2);
        }
    }

    // Finalize
    const int lc = (lane & 3) * 2;
    float inv[2];
    #pragma unroll
    for (int half = 0; half < 2; half++) {
        float l = lp[half];
        l += __shfl_xor_sync(0xffffffffu, l, 1);
        l += __shfl_xor_sync(0xffffffffu, l, 2);
        inv[half] = 1.f / l;
    }
    #pragma unroll
    for (int half = 0; half < 2; half++) {
        int i = i0 + w * 16 + lr + half * 8;
        __nv_bfloat16* orow = out + ((size_t)(b * NPOS + i)) * C_ + h * DHEAD;
        #pragma unroll
        for (int nv = 0; nv < 4; nv++) {
            __nv_bfloat162 pr = __floats2bfloat162_rn(
                oacc[nv][half * 2 + 0] * inv[half],
                oacc[nv][half * 2 + 1] * inv[half]);
            *(__nv_bfloat162*)&orow[nv * 8 + lc] = pr;
        }
    }
}

// ---------------------------------------------------------------------------
// Host launch
// ---------------------------------------------------------------------------
extern "C" void kernel_launch(void* const* d_in, const int* in_sizes, int n_in,
                              void* d_out, int out_size)
{
    const float* x       = (const float*)d_in[0];
    const float* qkv_w   = (const float*)d_in[1];
    const float* proj_w  = (const float*)d_in[2];
    const float* proj_b  = (const float*)d_in[3];
    const float* ffn_w1  = (const float*)d_in[4];
    const float* ffn_b1  = (const float*)d_in[5];
    const float* ffn_w2  = (const float*)d_in[6];
    const float* ffn_b2  = (const float*)d_in[7];
    const float* n1w     = (const float*)d_in[8];
    const float* n1b     = (const float*)d_in[9];
    const float* n2w     = (const float*)d_in[10];
    const float* n2b     = (const float*)d_in[11];
    const float* btab    = (const float*)d_in[12];
    const int*   ridx    = (const int*)d_in[13];
    float* out = (float*)d_out;

    float* scratch = nullptr;
    cudaGetSymbolAddress((void**)&scratch, g_scratch);

    __nv_bfloat16* wb    = (__nv_bfloat16*)(scratch + OFF_WB);
    __nv_bfloat16* x1b   = (__nv_bfloat16*)(scratch + OFF_X1B);
    __nv_bfloat16* qkvb  = (__nv_bfloat16*)(scratch + OFF_QKVB);
    __nv_bfloat16* bias8 = (__nv_bfloat16*)(scratch + OFF_BIAS8);
    __nv_bfloat16* attnb = (__nv_bfloat16*)(scratch + OFF_ATTNB);
    float*         x3    = scratch + OFF_X3;
    __nv_bfloat16* x4b   = (__nv_bfloat16*)(scratch + OFF_X4B);
    __nv_bfloat16* h1b   = (__nv_bfloat16*)(scratch + OFF_H1B);

    static bool attrSet = false;
    if (!attrSet) {
        cudaFuncSetAttribute(proj_ln_kernel,
                             cudaFuncAttributeMaxDynamicSharedMemorySize, PSMEM_BYTES);
        attrSet = true;
    }

    // 0. Weight conversion + bias precompute
    convert_w_kernel<<<(WB_TOTAL + 255) / 256, 256>>>(
        qkv_w, proj_w, ffn_w1, ffn_w2, wb);
    bias_pre<<<4096, 256>>>(btab, ridx, bias8);

    // 1. LN1 (fused transpose)
    ln1_kernel<<<dim3(NPOS / 32, B_), 256>>>(x, n1w, n1b, x1b);

    // 2. QKV GEMM -> bf16 q/k/v head layout
    mma_gemm<0><<<dim3(768 / 128, NTOK / 128), 128>>>(
        x1b, wb + WB_QKV, NTOK, 768, C_, nullptr, nullptr, nullptr, qkvb);

    // 3. Flash attention (pipelined S, Q-tile 64, 3 CTAs/SM)
    attn_mma<<<dim3(NPOS / 64, HEADS, B_), 128>>>(qkvb, bias8, attnb);

    // 4. Fused proj GEMM + bias + residual(x) + LN2 -> x3 / x4b
    proj_ln_kernel<<<NTOK / 128, 256, PSMEM_BYTES>>>(
        attnb, wb + WB_PROJ, proj_b, x, n2w, n2b, x3, x4b);

    // 5. FFN1 + GELU -> bf16 h1
    mma_gemm<2><<<dim3(HID / 128, NTOK / 128), 128>>>(
        x4b, wb + WB_W1, NTOK, HID, C_, ffn_b1, nullptr, nullptr, h1b);

    // 6. FFN2 + bias + residual(x3) -> fp32 output (B,C,H,W)
    mma_gemm<3><<<dim3(C_ / 128, NTOK / 128), 128>>>(
        h1b, wb + WB_W2, NTOK, C_, HID, ffn_b2, x3, out, nullptr);
}

// round 13
// speedup vs baseline: 1.0765x; 1.0765x over previous
#include <cuda_runtime.h>
#include <cuda_bf16.h>
#include <math.h>
#include <stdint.h>

// Problem constants
#define B_    16
#define C_    256
#define NTOK  16384
#define NPOS  1024
#define HEADS 8
#define DHEAD 32
#define HID   1024
#define LOG2E 1.4426950408889634f

// ---------------------------------------------------------------------------
// Scratch layout (float units)
// ---------------------------------------------------------------------------
#define OFF_WB     0u
#define WB_QKV     0u
#define WB_PROJ    196608u
#define WB_W1      262144u
#define WB_W2      524288u
#define WB_TOTAL   786432u

#define OFF_X1B    524288u
#define OFF_QKVB   2621440u
#define OFF_BIAS8  8912896u
#define OFF_ATTNB  13107200u
#define OFF_X3     15204352u
#define OFF_X4B    19398656u
#define OFF_H1B    21495808u
#define SCRATCH_FLOATS 33554432u

__device__ float g_scratch[SCRATCH_FLOATS];

// ---------------------------------------------------------------------------
// Merged prep: blocks [0, 3072) convert weights; blocks [3072, 7168) bias8.
// ---------------------------------------------------------------------------
__global__ __launch_bounds__(256)
void prep_kernel(const float* __restrict__ a, const float* __restrict__ b,
                 const float* __restrict__ c, const float* __restrict__ d,
                 __nv_bfloat16* __restrict__ wout,
                 const float* __restrict__ table, const int* __restrict__ ridx,
                 __nv_bfloat16* __restrict__ bias8)
{
    if (blockIdx.x < 3072) {
        unsigned i = blockIdx.x * 256u + threadIdx.x;
        if (i < WB_PROJ)            wout[i] = __float2bfloat16(a[i]);
        else if (i < WB_W1)         wout[i] = __float2bfloat16(b[i - WB_PROJ]);
        else if (i < WB_W2)         wout[i] = __float2bfloat16(c[i - WB_W1]);
        else if (i < WB_TOTAL)      wout[i] = __float2bfloat16(d[i - WB_W2]);
    } else {
        unsigned id = (blockIdx.x - 3072) * 256u + threadIdx.x;
        int idx = ridx[id];
        const float* tr = table + (size_t)idx * HEADS;
        #pragma unroll
        for (int h = 0; h < HEADS; h++)
            bias8[(size_t)h * 1048576u + id] = __float2bfloat16(tr[h] * LOG2E);
    }
}

// ---------------------------------------------------------------------------
// LN1: fused transpose LayerNorm (B,C,n) fp32 -> token-major bf16
// ---------------------------------------------------------------------------
__global__ __launch_bounds__(256)
void ln1_kernel(const float* __restrict__ in, const float* __restrict__ w,
                const float* __restrict__ bv, __nv_bfloat16* __restrict__ out)
{
    __shared__ float tile[C_][33];
    __shared__ float red1[8][32], red2[8][32];
    __shared__ float smu[32], srs[32];

    const int bb = blockIdx.y, p0 = blockIdx.x * 32;
    const int tid = threadIdx.x;

    #pragma unroll
    for (int it = 0; it < 32; it++) {
        int id = it * 256 + tid;
        int c = id >> 5, pp = id & 31;
        tile[c][pp] = in[((size_t)(bb * C_ + c)) * NPOS + p0 + pp];
    }
    __syncthreads();

    {
        int token = tid & 31, part = tid >> 5;
        float s1 = 0.f, s2 = 0.f;
        #pragma unroll
        for (int cc = 0; cc < 32; cc++) {
            float v = tile[part * 32 + cc][token];
            s1 += v; s2 += v * v;
        }
        red1[part][token] = s1;
        red2[part][token] = s2;
    }
    __syncthreads();
    if (tid < 32) {
        float t1 = 0.f, t2 = 0.f;
        #pragma unroll
        for (int p = 0; p < 8; p++) { t1 += red1[p][tid]; t2 += red2[p][tid]; }
        float mu  = t1 * (1.f / C_);
        float var = t2 * (1.f / C_) - mu * mu;
        smu[tid] = mu;
        srs[tid] = rsqrtf(var + 1e-5f);
    }
    __syncthreads();

    const float wc = w[tid], bc = bv[tid];
    #pragma unroll
    for (int it = 0; it < 32; it++) {
        float v = tile[tid][it];
        out[((size_t)(bb * NPOS + p0 + it)) * C_ + tid] =
            __float2bfloat16((v - smu[it]) * srs[it] * wc + bc);
    }
}

// ---------------------------------------------------------------------------
// bf16 mma.sync GEMM (128 thr / 4 warps, warp tile 64x64) — EPI 0/2/3
// ---------------------------------------------------------------------------
#define AKP 40
#define BNP 136

#define MMA16816(acc, af, b0, b1)                                              \
    asm volatile("mma.sync.aligned.m16n8k16.row.col.f32.bf16.bf16.f32 "        \
                 "{%0,%1,%2,%3}, {%4,%5,%6,%7}, {%8,%9}, {%0,%1,%2,%3};"       \
                 : "+f"(acc[0]), "+f"(acc[1]), "+f"(acc[2]), "+f"(acc[3])      \
                 : "r"(af[0]), "r"(af[1]), "r"(af[2]), "r"(af[3]),             \
                   "r"(b0), "r"(b1))

template<int EPI>
__global__ __launch_bounds__(128)
void mma_gemm(const __nv_bfloat16* __restrict__ A, const __nv_bfloat16* __restrict__ Bw,
              int M, int N, int K,
              const float* __restrict__ bias, const float* __restrict__ res,
              float* __restrict__ outf, __nv_bfloat16* __restrict__ outb)
{
    __shared__ __align__(16) __nv_bfloat16 As[3][128][AKP];
    __shared__ __align__(16) __nv_bfloat16 Bs[3][32][BNP];

    const int tid = threadIdx.x, lane = tid & 31, wid = tid >> 5;
    const int wm = wid >> 1, wn = wid & 1;
    const int m0 = blockIdx.y * 128, n0 = blockIdx.x * 128;

    float acc[4][8][4] = {};
    const int S = K >> 5;

    auto loadStage = [&](int s, int buf) {
        int kpos = s << 5;
        #pragma unroll
        for (int j = 0; j < 4; j++) {
            int id = tid + j * 128;
            int r = id >> 2, kc = id & 3;
            const __nv_bfloat16* g = A + (size_t)(m0 + r) * K + kpos + kc * 8;
            unsigned dst = (unsigned)__cvta_generic_to_shared(&As[buf][r][kc * 8]);
            asm volatile("cp.async.cg.shared.global [%0], [%1], 16;\n"
                         :: "r"(dst), "l"(g));
        }
        #pragma unroll
        for (int j = 0; j < 4; j++) {
            int id = tid + j * 128;
            int r = id >> 4, nc = id & 15;
            const __nv_bfloat16* g = Bw + (size_t)(kpos + r) * N + n0 + nc * 8;
            unsigned dst = (unsigned)__cvta_generic_to_shared(&Bs[buf][r][nc * 8]);
            asm volatile("cp.async.cg.shared.global [%0], [%1], 16;\n"
                         :: "r"(dst), "l"(g));
        }
        asm volatile("cp.async.commit_group;\n" ::: "memory");
    };

    loadStage(0, 0);
    loadStage(1, 1);

    int buf = 0;
    for (int s = 0; s < S; s++) {
        asm volatile("cp.async.wait_group 1;\n" ::: "memory");
        __syncthreads();
        if (s + 2 < S) {
            int nb = buf + 2; if (nb >= 3) nb -= 3;
            loadStage(s + 2, nb);
        }

        #pragma unroll
        for (int ks = 0; ks < 2; ks++) {
            const int kb = ks * 16;
            unsigned afr[4][4];
            #pragma unroll
            for (int mt = 0; mt < 4; mt++) {
                unsigned ad = (unsigned)__cvta_generic_to_shared(
                    &As[buf][wm * 64 + mt * 16 + (lane & 15)][kb + (lane >> 4) * 8]);
                asm volatile("ldmatrix.sync.aligned.m8n8.x4.shared.b16 {%0,%1,%2,%3}, [%4];"
                             : "=r"(afr[mt][0]), "=r"(afr[mt][1]),
                               "=r"(afr[mt][2]), "=r"(afr[mt][3]) : "r"(ad));
            }
            unsigned bfr[8][2];
            #pragma unroll
            for (int np = 0; np < 4; np++) {
                int quad = lane >> 3, rr = lane & 7;
                int row = kb + (quad & 1) * 8 + rr;
                int col = wn * 64 + np * 16 + (quad >> 1) * 8;
                unsigned bd = (unsigned)__cvta_generic_to_shared(&Bs[buf][row][col]);
                asm volatile("ldmatrix.sync.aligned.m8n8.x4.trans.shared.b16 {%0,%1,%2,%3}, [%4];"
                             : "=r"(bfr[np * 2][0]), "=r"(bfr[np * 2][1]),
                               "=r"(bfr[np * 2 + 1][0]), "=r"(bfr[np * 2 + 1][1]) : "r"(bd));
            }
            #pragma unroll
            for (int mt = 0; mt < 4; mt++)
                #pragma unroll
                for (int nt = 0; nt < 8; nt++)
                    MMA16816(acc[mt][nt], afr[mt], bfr[nt][0], bfr[nt][1]);
        }
        buf++; if (buf >= 3) buf = 0;
    }

    const int lr = lane >> 2, lc = (lane & 3) * 2;
    #pragma unroll
    for (int mt = 0; mt < 4; mt++) {
        #pragma unroll
        for (int half = 0; half < 2; half++) {
            int mrow = m0 + wm * 64 + mt * 16 + lr + half * 8;
            int bb = mrow >> 10, p = mrow & 1023;
            #pragma unroll
            for (int nt = 0; nt < 8; nt++) {
                if (EPI == 0) {
                    int c = n0 + wn * 64 + nt * 8 + lc;
                    int part = c >> 8, hh = (c >> 5) & 7, d = c & 31;
                    __nv_bfloat162 pr = __floats2bfloat162_rn(
                        acc[mt][nt][half * 2 + 0], acc[mt][nt][half * 2 + 1]);
                    *(__nv_bfloat162*)&outb[(size_t)part * 4194304u +
                        (((size_t)(bb * HEADS + hh)) * NPOS + p) * DHEAD + d] = pr;
                } else {
                    #pragma unroll
                    for (int e = 0; e < 2; e++) {
                        int c = n0 + wn * 64 + nt * 8 + lc + e;
                        float v = acc[mt][nt][half * 2 + e];
                        if (EPI == 2) {
                            float t = v + bias[c];
                            outb[(size_t)mrow * N + c] = __float2bfloat16(
                                0.5f * t * (1.f + erff(t * 0.70710678118654752f)));
                        } else {
                            outf[((size_t)(bb * C_ + c)) * NPOS + p] =
                                v + bias[c] + res[(size_t)mrow * C_ + c];
                        }
                    }
                }
            }
        }
    }
}

// ---------------------------------------------------------------------------
// Fused proj GEMM + bias + residual + LayerNorm2.
// CTA tile 64x256 (full channel row), 256 threads / 8 warps (2x4),
// warp tile 32x64 — grid 256 CTAs for better chip utilization.
// ---------------------------------------------------------------------------
#define PBNP 264
#define PA_STG (64 * AKP)
#define PB_STG (32 * PBNP)
#define PSMEM_BYTES ((3 * PA_STG + 3 * PB_STG) * 2)

__global__ __launch_bounds__(256)
void proj_ln_kernel(const __nv_bfloat16* __restrict__ A, const __nv_bfloat16* __restrict__ Bw,
                    const float* __restrict__ bias, const float* __restrict__ res,
                    const float* __restrict__ n2w, const float* __restrict__ n2b,
                    float* __restrict__ x3, __nv_bfloat16* __restrict__ x4b)
{
    extern __shared__ __align__(16) __nv_bfloat16 dsm[];
    __nv_bfloat16* AsBase = dsm;
    __nv_bfloat16* BsBase = dsm + 3 * PA_STG;
    __shared__ float sum4[4][64], sq4[4][64];
    __shared__ float smu[64], srs[64];

    const int tid = threadIdx.x, lane = tid & 31, wid = tid >> 5;
    const int wm = wid >> 2, wn = wid & 3;     // 2 x 4 warps, 32x64 tiles
    const int m0 = blockIdx.x * 64;
    const int K = C_, N = C_;

    float acc[2][8][4] = {};

    auto loadStage = [&](int s, int buf) {
        int kpos = s << 5;
        __nv_bfloat16* As = AsBase + buf * PA_STG;
        __nv_bfloat16* Bs = BsBase + buf * PB_STG;
        {
            int r = tid >> 2, kc = tid & 3;   // 256 threads: 64 rows x 4 chunks
            const __nv_bfloat16* g = A + (size_t)(m0 + r) * K + kpos + kc * 8;
            unsigned dst = (unsigned)__cvta_generic_to_shared(As + r * AKP + kc * 8);
            asm volatile("cp.async.cg.shared.global [%0], [%1], 16;\n" :: "r"(dst), "l"(g));
        }
        #pragma unroll
        for (int j = 0; j < 4; j++) {
            int id = tid + j * 256;
            int r = id >> 5, nc = id & 31;
            const __nv_bfloat16* g = Bw + (size_t)(kpos + r) * N + nc * 8;
            unsigned dst = (unsigned)__cvta_generic_to_shared(Bs + r * PBNP + nc * 8);
            asm volatile("cp.async.cg.shared.global [%0], [%1], 16;\n" :: "r"(dst), "l"(g));
        }
        asm volatile("cp.async.commit_group;\n" ::: "memory");
    };

    loadStage(0, 0);
    loadStage(1, 1);

    int buf = 0;
    const int S = K >> 5;
    for (int s = 0; s < S; s++) {
        asm volatile("cp.async.wait_group 1;\n" ::: "memory");
        __syncthreads();
        if (s + 2 < S) {
            int nb = buf + 2; if (nb >= 3) nb -= 3;
            loadStage(s + 2, nb);
        }
        __nv_bfloat16* As = AsBase + buf * PA_STG;
        __nv_bfloat16* Bs = BsBase + buf * PB_STG;

        #pragma unroll
        for (int ks = 0; ks < 2; ks++) {
            const int kb = ks * 16;
            unsigned afr[2][4];
            #pragma unroll
            for (int mt = 0; mt < 2; mt++) {
                unsigned ad = (unsigned)__cvta_generic_to_shared(
                    As + (wm * 32 + mt * 16 + (lane & 15)) * AKP + kb + (lane >> 4) * 8);
                asm volatile("ldmatrix.sync.aligned.m8n8.x4.shared.b16 {%0,%1,%2,%3}, [%4];"
                             : "=r"(afr[mt][0]), "=r"(afr[mt][1]),
                               "=r"(afr[mt][2]), "=r"(afr[mt][3]) : "r"(ad));
            }
            unsigned bfr[8][2];
            #pragma unroll
            for (int np = 0; np < 4; np++) {
                int quad = lane >> 3, rr = lane & 7;
                int row = kb + (quad & 1) * 8 + rr;
                int col = wn * 64 + np * 16 + (quad >> 1) * 8;
                unsigned bd = (unsigned)__cvta_generic_to_shared(Bs + row * PBNP + col);
                asm volatile("ldmatrix.sync.aligned.m8n8.x4.trans.shared.b16 {%0,%1,%2,%3}, [%4];"
                             : "=r"(bfr[np * 2][0]), "=r"(bfr[np * 2][1]),
                               "=r"(bfr[np * 2 + 1][0]), "=r"(bfr[np * 2 + 1][1]) : "r"(bd));
            }
            #pragma unroll
            for (int mt = 0; mt < 2; mt++)
                #pragma unroll
                for (int nt = 0; nt < 8; nt++)
                    MMA16816(acc[mt][nt], afr[mt], bfr[nt][0], bfr[nt][1]);
        }
        buf++; if (buf >= 3) buf = 0;
    }

    const int lr = lane >> 2, lc = (lane & 3) * 2;

    #pragma unroll
    for (int mt = 0; mt < 2; mt++) {
        #pragma unroll
        for (int half = 0; half < 2; half++) {
            int mrow = m0 + wm * 32 + mt * 16 + lr + half * 8;
            int bb = mrow >> 10, p = mrow & 1023;
            float s1 = 0.f, s2 = 0.f;
            #pragma unroll
            for (int nt = 0; nt < 8; nt++) {
                #pragma unroll
                for (int e = 0; e < 2; e++) {
                    int c = wn * 64 + nt * 8 + lc + e;
                    float t = acc[mt][nt][half * 2 + e] + bias[c] +
                              res[((size_t)(bb * C_ + c)) * NPOS + p];
                    acc[mt][nt][half * 2 + e] = t;
                    s1 += t; s2 += t * t;
                }
            }
            s1 += __shfl_xor_sync(0xffffffffu, s1, 1);
            s2 += __shfl_xor_sync(0xffffffffu, s2, 1);
            s1 += __shfl_xor_sync(0xffffffffu, s1, 2);
            s2 += __shfl_xor_sync(0xffffffffu, s2, 2);
            if ((lane & 3) == 0) {
                int r = wm * 32 + mt * 16 + lr + half * 8;
                sum4[wn][r] = s1;
                sq4[wn][r] = s2;
            }
        }
    }
    __syncthreads();
    if (tid < 64) {
        float t1 = sum4[0][tid] + sum4[1][tid] + sum4[2][tid] + sum4[3][tid];
        float t2 = sq4[0][tid] + sq4[1][tid] + sq4[2][tid] + sq4[3][tid];
        float mu  = t1 * (1.f / C_);
        float var = t2 * (1.f / C_) - mu * mu;
        smu[tid] = mu;
        srs[tid] = rsqrtf(var + 1e-5f);
    }
    __syncthreads();

    #pragma unroll
    for (int mt = 0; mt < 2; mt++) {
        #pragma unroll
        for (int half = 0; half < 2; half++) {
            int r = wm * 32 + mt * 16 + lr + half * 8;
            int mrow = m0 + r;
            float mu = smu[r], rs = srs[r];
            #pragma unroll
            for (int nt = 0; nt < 8; nt++) {
                int c = wn * 64 + nt * 8 + lc;
                float t0 = acc[mt][nt][half * 2 + 0];
                float t1v = acc[mt][nt][half * 2 + 1];
                *(float2*)&x3[(size_t)mrow * C_ + c] = make_float2(t0, t1v);
                float g0 = (t0 - mu) * rs * n2w[c] + n2b[c];
                float g1 = (t1v - mu) * rs * n2w[c + 1] + n2b[c + 1];
                __nv_bfloat162 pr = __floats2bfloat162_rn(g0, g1);
                *(__nv_bfloat162*)&x4b[(size_t)mrow * C_ + c] = pr;
            }
        }
    }
}

// ---------------------------------------------------------------------------
// Tensor-core flash attention — exact R11 version (best measured).
// Q-tile 64, 128 threads / 4 warps, 3 CTAs/SM.
// ---------------------------------------------------------------------------
__global__ __launch_bounds__(128, 3)
void attn_mma(const __nv_bfloat16* __restrict__ qkv,
              const __nv_bfloat16* __restrict__ bias8,
              __nv_bfloat16* __restrict__ out)
{
    __shared__ __align__(16) __nv_bfloat16 Qs[64][40];
    __shared__ __align__(16) __nv_bfloat16 Ks[3][64][40];
    __shared__ __align__(16) __nv_bfloat16 Vs[3][64][40];

    const int tid = threadIdx.x, lane = tid & 31, w = tid >> 5;
    const int qt = blockIdx.x, h = blockIdx.y, b = blockIdx.z;
    const int i0 = qt * 64;
    const size_t headBase = ((size_t)(b * HEADS + h)) * NPOS * DHEAD;
    const __nv_bfloat16* qg = qkv + headBase;
    const __nv_bfloat16* kg = qkv + 4194304u + headBase;
    const __nv_bfloat16* vg = qkv + 8388608u + headBase;

    {
        int id = tid;
        #pragma unroll
        for (int it = 0; it < 2; it++, id += 128) {
            int r = id >> 2, kc = id & 3;
            const __nv_bfloat16* g = qg + (size_t)(i0 + r) * DHEAD + kc * 8;
            unsigned dst = (unsigned)__cvta_generic_to_shared(&Qs[r][kc * 8]);
            asm volatile("cp.async.cg.shared.global [%0], [%1], 16;\n" :: "r"(dst), "l"(g));
        }
        asm volatile("cp.async.commit_group;\n" ::: "memory");
    }

    auto loadKV = [&](int t, int buf) {
        int j0 = t * 64;
        #pragma unroll
        for (int it = 0; it < 2; it++) {
            int id = tid + it * 128;
            int r = id >> 2, kc = id & 3;
            const __nv_bfloat16* gk = kg + (size_t)(j0 + r) * DHEAD + kc * 8;
            unsigned dk = (unsigned)__cvta_generic_to_shared(&Ks[buf][r][kc * 8]);
            asm volatile("cp.async.cg.shared.global [%0], [%1], 16;\n" :: "r"(dk), "l"(gk));
            const __nv_bfloat16* gv = vg + (size_t)(j0 + r) * DHEAD + kc * 8;
            unsigned dv = (unsigned)__cvta_generic_to_shared(&Vs[buf][r][kc * 8]);
            asm volatile("cp.async.cg.shared.global [%0], [%1], 16;\n" :: "r"(dv), "l"(gv));
        }
        asm volatile("cp.async.commit_group;\n" ::: "memory");
    };

    loadKV(0, 0);

    unsigned qf[2][4];
    float oacc[4][4] = {};
    float lp[2] = {0.f, 0.f};
    const int lr = lane >> 2, lc = (lane & 3) * 2;
    const float k1 = 0.17677669529663687f * LOG2E;
    const __nv_bfloat162 k2 = __float2bfloat162_rn(k1);
    const __nv_bfloat16* bp = bias8 + ((size_t)h << 20);

    int kbuf = 0;
    for (int t = 0; t < 16; t++) {
        if (t + 1 < 16) {
            int nb = kbuf + 1; if (nb == 3) nb = 0;
            loadKV(t + 1, nb);
            asm volatile("cp.async.wait_group 1;\n" ::: "memory");
        } else {
            asm volatile("cp.async.wait_group 0;\n" ::: "memory");
        }
        __syncthreads();

        unsigned breg[2][8];
        #pragma unroll
        for (int half = 0; half < 2; half++) {
            const __nv_bfloat16* brow =
                bp + (size_t)(i0 + w * 16 + lr + half * 8) * NPOS + t * 64;
            #pragma unroll
            for (int nt = 0; nt < 8; nt++)
                breg[half][nt] = *(const unsigned*)(brow + nt * 8 + lc);
        }

        if (t == 0) {
            #pragma unroll
            for (int kk = 0; kk < 2; kk++) {
                unsigned ad = (unsigned)__cvta_generic_to_shared(
                    &Qs[w * 16 + (lane & 15)][kk * 16 + (lane >> 4) * 8]);
                asm volatile("ldmatrix.sync.aligned.m8n8.x4.shared.b16 {%0,%1,%2,%3}, [%4];"
                             : "=r"(qf[kk][0]), "=r"(qf[kk][1]),
                               "=r"(qf[kk][2]), "=r"(qf[kk][3]) : "r"(ad));
            }
        }

        float sacc[8][4] = {};
        #pragma unroll
        for (int kk = 0; kk < 2; kk++) {
            unsigned bfr[8][2];
            #pragma unroll
            for (int np = 0; np < 4; np++) {
                int g = lane >> 3;
                unsigned ad = (unsigned)__cvta_generic_to_shared(
                    &Ks[kbuf][(np * 2 + (g >> 1)) * 8 + (lane & 7)][kk * 16 + (g & 1) * 8]);
                asm volatile("ldmatrix.sync.aligned.m8n8.x4.shared.b16 {%0,%1,%2,%3}, [%4];"
                             : "=r"(bfr[np * 2][0]), "=r"(bfr[np * 2][1]),
                               "=r"(bfr[np * 2 + 1][0]), "=r"(bfr[np * 2 + 1][1]) : "r"(ad));
            }
            #pragma unroll
            for (int nt = 0; nt < 8; nt++)
                MMA16816(sacc[nt], qf[kk], bfr[nt][0], bfr[nt][1]);
        }

        unsigned pfr[8][2];
        #pragma unroll
        for (int half = 0; half < 2; half++) {
            float rsum = 0.f;
            #pragma unroll
            for (int nt = 0; nt < 8; nt++) {
                __nv_bfloat162 bbv = *reinterpret_cast<__nv_bfloat162*>(&breg[half][nt]);
                __nv_bfloat162 s2 = __floats2bfloat162_rn(
                    sacc[nt][half * 2 + 0], sacc[nt][half * 2 + 1]);
                __nv_bfloat162 arg = __hfma2(s2, k2, bbv);
                unsigned argr = *reinterpret_cast<unsigned*>(&arg);
                unsigned p2r;
                asm("ex2.approx.ftz.bf16x2 %0, %1;" : "=r"(p2r) : "r"(argr));
                pfr[nt][half] = p2r;
                float2 pf2 = __bfloat1622float2(*reinterpret_cast<__nv_bfloat162*>(&p2r));
                rsum += pf2.x + pf2.y;
            }
            lp[half] += rsum;
        }

        #pragma unroll
        for (int kc = 0; kc < 4; kc++) {
            unsigned pf[4];
            pf[0] = pfr[2 * kc][0];
            pf[1] = pfr[2 * kc][1];
            pf[2] = pfr[2 * kc + 1][0];
            pf[3] = pfr[2 * kc + 1][1];

            unsigned bv[4][2];
            #pragma unroll
            for (int np = 0; np < 2; np++) {
                int quad = lane >> 3, rr = lane & 7;
                unsigned ad = (unsigned)__cvta_generic_to_shared(
                    &Vs[kbuf][kc * 16 + (quad & 1) * 8 + rr][np * 16 + (quad >> 1) * 8]);
                asm volatile("ldmatrix.sync.aligned.m8n8.x4.trans.shared.b16 {%0,%1,%2,%3}, [%4];"
                             : "=r"(bv[np * 2][0]), "=r"(bv[np * 2][1]),
                               "=r"(bv[np * 2 + 1][0]), "=r"(bv[np * 2 + 1][1]) : "r"(ad));
            }
            #pragma unroll
            for (int nv = 0; nv < 4; nv++)
                MMA16816(oacc[nv], pf, bv[nv][0], bv[nv][1]);
        }

        kbuf++; if (kbuf == 3) kbuf = 0;
    }

    float inv[2];
    #pragma unroll
    for (int half = 0; half < 2; half++) {
        float l = lp[half];
        l += __shfl_xor_sync(0xffffffffu, l, 1);
        l += __shfl_xor_sync(0xffffffffu, l, 2);
        inv[half] = 1.f / l;
    }
    #pragma unroll
    for (int half = 0; half < 2; half++) {
        int i = i0 + w * 16 + lr + half * 8;
        __nv_bfloat16* orow = out + ((size_t)(b * NPOS + i)) * C_ + h * DHEAD;
        #pragma unroll
        for (int nv = 0; nv < 4; nv++) {
            __nv_bfloat162 pr = __floats2bfloat162_rn(
                oacc[nv][half * 2 + 0] * inv[half],
                oacc[nv][half * 2 + 1] * inv[half]);
            *(__nv_bfloat162*)&orow[nv * 8 + lc] = pr;
        }
    }
}

// ---------------------------------------------------------------------------
// Host launch
// ---------------------------------------------------------------------------
extern "C" void kernel_launch(void* const* d_in, const int* in_sizes, int n_in,
                              void* d_out, int out_size)
{
    const float* x       = (const float*)d_in[0];
    const float* qkv_w   = (const float*)d_in[1];
    const float* proj_w  = (const float*)d_in[2];
    const float* proj_b  = (const float*)d_in[3];
    const float* ffn_w1  = (const float*)d_in[4];
    const float* ffn_b1  = (const float*)d_in[5];
    const float* ffn_w2  = (const float*)d_in[6];
    const float* ffn_b2  = (const float*)d_in[7];
    const float* n1w     = (const float*)d_in[8];
    const float* n1b     = (const float*)d_in[9];
    const float* n2w     = (const float*)d_in[10];
    const float* n2b     = (const float*)d_in[11];
    const float* btab    = (const float*)d_in[12];
    const int*   ridx    = (const int*)d_in[13];
    float* out = (float*)d_out;

    float* scratch = nullptr;
    cudaGetSymbolAddress((void**)&scratch, g_scratch);

    __nv_bfloat16* wb    = (__nv_bfloat16*)(scratch + OFF_WB);
    __nv_bfloat16* x1b   = (__nv_bfloat16*)(scratch + OFF_X1B);
    __nv_bfloat16* qkvb  = (__nv_bfloat16*)(scratch + OFF_QKVB);
    __nv_bfloat16* bias8 = (__nv_bfloat16*)(scratch + OFF_BIAS8);
    __nv_bfloat16* attnb = (__nv_bfloat16*)(scratch + OFF_ATTNB);
    float*         x3    = scratch + OFF_X3;
    __nv_bfloat16* x4b   = (__nv_bfloat16*)(scratch + OFF_X4B);
    __nv_bfloat16* h1b   = (__nv_bfloat16*)(scratch + OFF_H1B);

    static bool attrSet = false;
    if (!attrSet) {
        cudaFuncSetAttribute(proj_ln_kernel,
                             cudaFuncAttributeMaxDynamicSharedMemorySize, PSMEM_BYTES);
        attrSet = true;
    }

    // 0. Merged prep: weight conversion + bias precompute
    prep_kernel<<<7168, 256>>>(qkv_w, proj_w, ffn_w1, ffn_w2, wb, btab, ridx, bias8);

    // 1. LN1 (fused transpose)
    ln1_kernel<<<dim3(NPOS / 32, B_), 256>>>(x, n1w, n1b, x1b);

    // 2. QKV GEMM -> bf16 q/k/v head layout
    mma_gemm<0><<<dim3(768 / 128, NTOK / 128), 128>>>(
        x1b, wb + WB_QKV, NTOK, 768, C_, nullptr, nullptr, nullptr, qkvb);

    // 3. Flash attention (Q-tile 64, 3 CTAs/SM)
    attn_mma<<<dim3(NPOS / 64, HEADS, B_), 128>>>(qkvb, bias8, attnb);

    // 4. Fused proj GEMM + bias + residual(x) + LN2 -> x3 / x4b (64-row CTAs)
    proj_ln_kernel<<<NTOK / 64, 256, PSMEM_BYTES>>>(
        attnb, wb + WB_PROJ, proj_b, x, n2w, n2b, x3, x4b);

    // 5. FFN1 + GELU -> bf16 h1
    mma_gemm<2><<<dim3(HID / 128, NTOK / 128), 128>>>(
        x4b, wb + WB_W1, NTOK, HID, C_, ffn_b1, nullptr, nullptr, h1b);

    // 6. FFN2 + bias + residual(x3) -> fp32 output (B,C,H,W)
    mma_gemm<3><<<dim3(C_ / 128, NTOK / 128), 128>>>(
        h1b, wb + WB_W2, NTOK, C_, HID, ffn_b2, x3, out, nullptr);
}

// round 14
// speedup vs baseline: 1.1266x; 1.0466x over previous
#include <cuda_runtime.h>
#include <cuda_bf16.h>
#include <math.h>
#include <stdint.h>

// Problem constants
#define B_    16
#define C_    256
#define NTOK  16384
#define NPOS  1024
#define HEADS 8
#define DHEAD 32
#define HID   1024
#define LOG2E 1.4426950408889634f

// ---------------------------------------------------------------------------
// Scratch layout (float units)
// ---------------------------------------------------------------------------
#define OFF_WB     0u
#define WB_QKV     0u
#define WB_PROJ    196608u
#define WB_W1      262144u
#define WB_W2      524288u
#define WB_TOTAL   786432u

#define OFF_X1B    524288u
#define OFF_QKVB   2621440u
#define OFF_BIAS8  8912896u
#define OFF_ATTNB  13107200u
#define OFF_X3     15204352u
#define OFF_X4B    19398656u
#define OFF_H1B    21495808u
#define SCRATCH_FLOATS 33554432u

__device__ float g_scratch[SCRATCH_FLOATS];

// ---------------------------------------------------------------------------
// Merged prep: blocks [0, 3072) convert weights; blocks [3072, 7168) bias8.
// ---------------------------------------------------------------------------
__global__ __launch_bounds__(256)
void prep_kernel(const float* __restrict__ a, const float* __restrict__ b,
                 const float* __restrict__ c, const float* __restrict__ d,
                 __nv_bfloat16* __restrict__ wout,
                 const float* __restrict__ table, const int* __restrict__ ridx,
                 __nv_bfloat16* __restrict__ bias8)
{
    if (blockIdx.x < 3072) {
        unsigned i = blockIdx.x * 256u + threadIdx.x;
        if (i < WB_PROJ)            wout[i] = __float2bfloat16(a[i]);
        else if (i < WB_W1)         wout[i] = __float2bfloat16(b[i - WB_PROJ]);
        else if (i < WB_W2)         wout[i] = __float2bfloat16(c[i - WB_W1]);
        else if (i < WB_TOTAL)      wout[i] = __float2bfloat16(d[i - WB_W2]);
    } else {
        unsigned id = (blockIdx.x - 3072) * 256u + threadIdx.x;
        int idx = ridx[id];
        const float* tr = table + (size_t)idx * HEADS;
        #pragma unroll
        for (int h = 0; h < HEADS; h++)
            bias8[(size_t)h * 1048576u + id] = __float2bfloat16(tr[h] * LOG2E);
    }
}

// ---------------------------------------------------------------------------
// LN1: fused transpose LayerNorm (B,C,n) fp32 -> token-major bf16
// ---------------------------------------------------------------------------
__global__ __launch_bounds__(256)
void ln1_kernel(const float* __restrict__ in, const float* __restrict__ w,
                const float* __restrict__ bv, __nv_bfloat16* __restrict__ out)
{
    __shared__ float tile[C_][33];
    __shared__ float red1[8][32], red2[8][32];
    __shared__ float smu[32], srs[32];

    const int bb = blockIdx.y, p0 = blockIdx.x * 32;
    const int tid = threadIdx.x;

    #pragma unroll
    for (int it = 0; it < 32; it++) {
        int id = it * 256 + tid;
        int c = id >> 5, pp = id & 31;
        tile[c][pp] = in[((size_t)(bb * C_ + c)) * NPOS + p0 + pp];
    }
    __syncthreads();

    {
        int token = tid & 31, part = tid >> 5;
        float s1 = 0.f, s2 = 0.f;
        #pragma unroll
        for (int cc = 0; cc < 32; cc++) {
            float v = tile[part * 32 + cc][token];
            s1 += v; s2 += v * v;
        }
        red1[part][token] = s1;
        red2[part][token] = s2;
    }
    __syncthreads();
    if (tid < 32) {
        float t1 = 0.f, t2 = 0.f;
        #pragma unroll
        for (int p = 0; p < 8; p++) { t1 += red1[p][tid]; t2 += red2[p][tid]; }
        float mu  = t1 * (1.f / C_);
        float var = t2 * (1.f / C_) - mu * mu;
        smu[tid] = mu;
        srs[tid] = rsqrtf(var + 1e-5f);
    }
    __syncthreads();

    const float wc = w[tid], bc = bv[tid];
    #pragma unroll
    for (int it = 0; it < 32; it++) {
        float v = tile[tid][it];
        out[((size_t)(bb * NPOS + p0 + it)) * C_ + tid] =
            __float2bfloat16((v - smu[it]) * srs[it] * wc + bc);
    }
}

// ---------------------------------------------------------------------------
// bf16 mma.sync GEMM (128 thr / 4 warps, warp tile 64x64) — EPI 0/2/3
// ---------------------------------------------------------------------------
#define AKP 40
#define BNP 136

#define MMA16816(acc, af, b0, b1)                                              \
    asm volatile("mma.sync.aligned.m16n8k16.row.col.f32.bf16.bf16.f32 "        \
                 "{%0,%1,%2,%3}, {%4,%5,%6,%7}, {%8,%9}, {%0,%1,%2,%3};"       \
                 : "+f"(acc[0]), "+f"(acc[1]), "+f"(acc[2]), "+f"(acc[3])      \
                 : "r"(af[0]), "r"(af[1]), "r"(af[2]), "r"(af[3]),             \
                   "r"(b0), "r"(b1))

template<int EPI>
__global__ __launch_bounds__(128)
void mma_gemm(const __nv_bfloat16* __restrict__ A, const __nv_bfloat16* __restrict__ Bw,
              int M, int N, int K,
              const float* __restrict__ bias, const float* __restrict__ res,
              float* __restrict__ outf, __nv_bfloat16* __restrict__ outb)
{
    __shared__ __align__(16) __nv_bfloat16 As[3][128][AKP];
    __shared__ __align__(16) __nv_bfloat16 Bs[3][32][BNP];

    const int tid = threadIdx.x, lane = tid & 31, wid = tid >> 5;
    const int wm = wid >> 1, wn = wid & 1;
    const int m0 = blockIdx.y * 128, n0 = blockIdx.x * 128;

    float acc[4][8][4] = {};
    const int S = K >> 5;

    auto loadStage = [&](int s, int buf) {
        int kpos = s << 5;
        #pragma unroll
        for (int j = 0; j < 4; j++) {
            int id = tid + j * 128;
            int r = id >> 2, kc = id & 3;
            const __nv_bfloat16* g = A + (size_t)(m0 + r) * K + kpos + kc * 8;
            unsigned dst = (unsigned)__cvta_generic_to_shared(&As[buf][r][kc * 8]);
            asm volatile("cp.async.cg.shared.global [%0], [%1], 16;\n"
                         :: "r"(dst), "l"(g));
        }
        #pragma unroll
        for (int j = 0; j < 4; j++) {
            int id = tid + j * 128;
            int r = id >> 4, nc = id & 15;
            const __nv_bfloat16* g = Bw + (size_t)(kpos + r) * N + n0 + nc * 8;
            unsigned dst = (unsigned)__cvta_generic_to_shared(&Bs[buf][r][nc * 8]);
            asm volatile("cp.async.cg.shared.global [%0], [%1], 16;\n"
                         :: "r"(dst), "l"(g));
        }
        asm volatile("cp.async.commit_group;\n" ::: "memory");
    };

    loadStage(0, 0);
    loadStage(1, 1);

    int buf = 0;
    for (int s = 0; s < S; s++) {
        asm volatile("cp.async.wait_group 1;\n" ::: "memory");
        __syncthreads();
        if (s + 2 < S) {
            int nb = buf + 2; if (nb >= 3) nb -= 3;
            loadStage(s + 2, nb);
        }

        #pragma unroll
        for (int ks = 0; ks < 2; ks++) {
            const int kb = ks * 16;
            unsigned afr[4][4];
            #pragma unroll
            for (int mt = 0; mt < 4; mt++) {
                unsigned ad = (unsigned)__cvta_generic_to_shared(
                    &As[buf][wm * 64 + mt * 16 + (lane & 15)][kb + (lane >> 4) * 8]);
                asm volatile("ldmatrix.sync.aligned.m8n8.x4.shared.b16 {%0,%1,%2,%3}, [%4];"
                             : "=r"(afr[mt][0]), "=r"(afr[mt][1]),
                               "=r"(afr[mt][2]), "=r"(afr[mt][3]) : "r"(ad));
            }
            unsigned bfr[8][2];
            #pragma unroll
            for (int np = 0; np < 4; np++) {
                int quad = lane >> 3, rr = lane & 7;
                int row = kb + (quad & 1) * 8 + rr;
                int col = wn * 64 + np * 16 + (quad >> 1) * 8;
                unsigned bd = (unsigned)__cvta_generic_to_shared(&Bs[buf][row][col]);
                asm volatile("ldmatrix.sync.aligned.m8n8.x4.trans.shared.b16 {%0,%1,%2,%3}, [%4];"
                             : "=r"(bfr[np * 2][0]), "=r"(bfr[np * 2][1]),
                               "=r"(bfr[np * 2 + 1][0]), "=r"(bfr[np * 2 + 1][1]) : "r"(bd));
            }
            #pragma unroll
            for (int mt = 0; mt < 4; mt++)
                #pragma unroll
                for (int nt = 0; nt < 8; nt++)
                    MMA16816(acc[mt][nt], afr[mt], bfr[nt][0], bfr[nt][1]);
        }
        buf++; if (buf >= 3) buf = 0;
    }

    const int lr = lane >> 2, lc = (lane & 3) * 2;
    #pragma unroll
    for (int mt = 0; mt < 4; mt++) {
        #pragma unroll
        for (int half = 0; half < 2; half++) {
            int mrow = m0 + wm * 64 + mt * 16 + lr + half * 8;
            int bb = mrow >> 10, p = mrow & 1023;
            #pragma unroll
            for (int nt = 0; nt < 8; nt++) {
                if (EPI == 0) {
                    int c = n0 + wn * 64 + nt * 8 + lc;
                    int part = c >> 8, hh = (c >> 5) & 7, d = c & 31;
                    __nv_bfloat162 pr = __floats2bfloat162_rn(
                        acc[mt][nt][half * 2 + 0], acc[mt][nt][half * 2 + 1]);
                    *(__nv_bfloat162*)&outb[(size_t)part * 4194304u +
                        (((size_t)(bb * HEADS + hh)) * NPOS + p) * DHEAD + d] = pr;
                } else {
                    #pragma unroll
                    for (int e = 0; e < 2; e++) {
                        int c = n0 + wn * 64 + nt * 8 + lc + e;
                        float v = acc[mt][nt][half * 2 + e];
                        if (EPI == 2) {
                            float t = v + bias[c];
                            outb[(size_t)mrow * N + c] = __float2bfloat16(
                                0.5f * t * (1.f + erff(t * 0.70710678118654752f)));
                        } else {
                            outf[((size_t)(bb * C_ + c)) * NPOS + p] =
                                v + bias[c] + res[(size_t)mrow * C_ + c];
                        }
                    }
                }
            }
        }
    }
}

// ---------------------------------------------------------------------------
// Fused proj GEMM + bias + residual + LayerNorm2 (64-row CTAs, as R13)
// ---------------------------------------------------------------------------
#define PBNP 264
#define PA_STG (64 * AKP)
#define PB_STG (32 * PBNP)
#define PSMEM_BYTES ((3 * PA_STG + 3 * PB_STG) * 2)

__global__ __launch_bounds__(256)
void proj_ln_kernel(const __nv_bfloat16* __restrict__ A, const __nv_bfloat16* __restrict__ Bw,
                    const float* __restrict__ bias, const float* __restrict__ res,
                    const float* __restrict__ n2w, const float* __restrict__ n2b,
                    float* __restrict__ x3, __nv_bfloat16* __restrict__ x4b)
{
    extern __shared__ __align__(16) __nv_bfloat16 dsm[];
    __nv_bfloat16* AsBase = dsm;
    __nv_bfloat16* BsBase = dsm + 3 * PA_STG;
    __shared__ float sum4[4][64], sq4[4][64];
    __shared__ float smu[64], srs[64];

    const int tid = threadIdx.x, lane = tid & 31, wid = tid >> 5;
    const int wm = wid >> 2, wn = wid & 3;
    const int m0 = blockIdx.x * 64;
    const int K = C_, N = C_;

    float acc[2][8][4] = {};

    auto loadStage = [&](int s, int buf) {
        int kpos = s << 5;
        __nv_bfloat16* As = AsBase + buf * PA_STG;
        __nv_bfloat16* Bs = BsBase + buf * PB_STG;
        {
            int r = tid >> 2, kc = tid & 3;
            const __nv_bfloat16* g = A + (size_t)(m0 + r) * K + kpos + kc * 8;
            unsigned dst = (unsigned)__cvta_generic_to_shared(As + r * AKP + kc * 8);
            asm volatile("cp.async.cg.shared.global [%0], [%1], 16;\n" :: "r"(dst), "l"(g));
        }
        #pragma unroll
        for (int j = 0; j < 4; j++) {
            int id = tid + j * 256;
            int r = id >> 5, nc = id & 31;
            const __nv_bfloat16* g = Bw + (size_t)(kpos + r) * N + nc * 8;
            unsigned dst = (unsigned)__cvta_generic_to_shared(Bs + r * PBNP + nc * 8);
            asm volatile("cp.async.cg.shared.global [%0], [%1], 16;\n" :: "r"(dst), "l"(g));
        }
        asm volatile("cp.async.commit_group;\n" ::: "memory");
    };

    loadStage(0, 0);
    loadStage(1, 1);

    int buf = 0;
    const int S = K >> 5;
    for (int s = 0; s < S; s++) {
        asm volatile("cp.async.wait_group 1;\n" ::: "memory");
        __syncthreads();
        if (s + 2 < S) {
            int nb = buf + 2; if (nb >= 3) nb -= 3;
            loadStage(s + 2, nb);
        }
        __nv_bfloat16* As = AsBase + buf * PA_STG;
        __nv_bfloat16* Bs = BsBase + buf * PB_STG;

        #pragma unroll
        for (int ks = 0; ks < 2; ks++) {
            const int kb = ks * 16;
            unsigned afr[2][4];
            #pragma unroll
            for (int mt = 0; mt < 2; mt++) {
                unsigned ad = (unsigned)__cvta_generic_to_shared(
                    As + (wm * 32 + mt * 16 + (lane & 15)) * AKP + kb + (lane >> 4) * 8);
                asm volatile("ldmatrix.sync.aligned.m8n8.x4.shared.b16 {%0,%1,%2,%3}, [%4];"
                             : "=r"(afr[mt][0]), "=r"(afr[mt][1]),
                               "=r"(afr[mt][2]), "=r"(afr[mt][3]) : "r"(ad));
            }
            unsigned bfr[8][2];
            #pragma unroll
            for (int np = 0; np < 4; np++) {
                int quad = lane >> 3, rr = lane & 7;
                int row = kb + (quad & 1) * 8 + rr;
                int col = wn * 64 + np * 16 + (quad >> 1) * 8;
                unsigned bd = (unsigned)__cvta_generic_to_shared(Bs + row * PBNP + col);
                asm volatile("ldmatrix.sync.aligned.m8n8.x4.trans.shared.b16 {%0,%1,%2,%3}, [%4];"
                             : "=r"(bfr[np * 2][0]), "=r"(bfr[np * 2][1]),
                               "=r"(bfr[np * 2 + 1][0]), "=r"(bfr[np * 2 + 1][1]) : "r"(bd));
            }
            #pragma unroll
            for (int mt = 0; mt < 2; mt++)
                #pragma unroll
                for (int nt = 0; nt < 8; nt++)
                    MMA16816(acc[mt][nt], afr[mt], bfr[nt][0], bfr[nt][1]);
        }
        buf++; if (buf >= 3) buf = 0;
    }

    const int lr = lane >> 2, lc = (lane & 3) * 2;

    #pragma unroll
    for (int mt = 0; mt < 2; mt++) {
        #pragma unroll
        for (int half = 0; half < 2; half++) {
            int mrow = m0 + wm * 32 + mt * 16 + lr + half * 8;
            int bb = mrow >> 10, p = mrow & 1023;
            float s1 = 0.f, s2 = 0.f;
            #pragma unroll
            for (int nt = 0; nt < 8; nt++) {
                #pragma unroll
                for (int e = 0; e < 2; e++) {
                    int c = wn * 64 + nt * 8 + lc + e;
                    float t = acc[mt][nt][half * 2 + e] + bias[c] +
                              res[((size_t)(bb * C_ + c)) * NPOS + p];
                    acc[mt][nt][half * 2 + e] = t;
                    s1 += t; s2 += t * t;
                }
            }
            s1 += __shfl_xor_sync(0xffffffffu, s1, 1);
            s2 += __shfl_xor_sync(0xffffffffu, s2, 1);
            s1 += __shfl_xor_sync(0xffffffffu, s1, 2);
            s2 += __shfl_xor_sync(0xffffffffu, s2, 2);
            if ((lane & 3) == 0) {
                int r = wm * 32 + mt * 16 + lr + half * 8;
                sum4[wn][r] = s1;
                sq4[wn][r] = s2;
            }
        }
    }
    __syncthreads();
    if (tid < 64) {
        float t1 = sum4[0][tid] + sum4[1][tid] + sum4[2][tid] + sum4[3][tid];
        float t2 = sq4[0][tid] + sq4[1][tid] + sq4[2][tid] + sq4[3][tid];
        float mu  = t1 * (1.f / C_);
        float var = t2 * (1.f / C_) - mu * mu;
        smu[tid] = mu;
        srs[tid] = rsqrtf(var + 1e-5f);
    }
    __syncthreads();

    #pragma unroll
    for (int mt = 0; mt < 2; mt++) {
        #pragma unroll
        for (int half = 0; half < 2; half++) {
            int r = wm * 32 + mt * 16 + lr + half * 8;
            int mrow = m0 + r;
            float mu = smu[r], rs = srs[r];
            #pragma unroll
            for (int nt = 0; nt < 8; nt++) {
                int c = wn * 64 + nt * 8 + lc;
                float t0 = acc[mt][nt][half * 2 + 0];
                float t1v = acc[mt][nt][half * 2 + 1];
                *(float2*)&x3[(size_t)mrow * C_ + c] = make_float2(t0, t1v);
                float g0 = (t0 - mu) * rs * n2w[c] + n2b[c];
                float g1 = (t1v - mu) * rs * n2w[c + 1] + n2b[c + 1];
                __nv_bfloat162 pr = __floats2bfloat162_rn(g0, g1);
                *(__nv_bfloat162*)&x4b[(size_t)mrow * C_ + c] = pr;
            }
        }
    }
}

// ---------------------------------------------------------------------------
// Tensor-core flash attention — Q-tile 128 / CTA, 128 thr / 4 warps,
// warp = 32 q-rows (2 m-tiles). K/V fragments loaded ONCE per warp per tile
// and reused for both m-tiles: halves L1/ldmatrix traffic per q-row.
// ---------------------------------------------------------------------------
__global__ __launch_bounds__(128, 3)
void attn_mma(const __nv_bfloat16* __restrict__ qkv,
              const __nv_bfloat16* __restrict__ bias8,
              __nv_bfloat16* __restrict__ out)
{
    __shared__ __align__(16) __nv_bfloat16 Qs[128][40];
    __shared__ __align__(16) __nv_bfloat16 Ks[3][64][40];
    __shared__ __align__(16) __nv_bfloat16 Vs[3][64][40];

    const int tid = threadIdx.x, lane = tid & 31, w = tid >> 5;
    const int qt = blockIdx.x, h = blockIdx.y, b = blockIdx.z;
    const int i0 = qt * 128;
    const size_t headBase = ((size_t)(b * HEADS + h)) * NPOS * DHEAD;
    const __nv_bfloat16* qg = qkv + headBase;
    const __nv_bfloat16* kg = qkv + 4194304u + headBase;
    const __nv_bfloat16* vg = qkv + 8388608u + headBase;

    // Q tile (128 rows) -> smem
    {
        int id = tid;
        #pragma unroll
        for (int it = 0; it < 4; it++, id += 128) {
            int r = id >> 2, kc = id & 3;
            const __nv_bfloat16* g = qg + (size_t)(i0 + r) * DHEAD + kc * 8;
            unsigned dst = (unsigned)__cvta_generic_to_shared(&Qs[r][kc * 8]);
            asm volatile("cp.async.cg.shared.global [%0], [%1], 16;\n" :: "r"(dst), "l"(g));
        }
        asm volatile("cp.async.commit_group;\n" ::: "memory");
    }

    auto loadKV = [&](int t, int buf) {
        int j0 = t * 64;
        #pragma unroll
        for (int it = 0; it < 2; it++) {
            int id = tid + it * 128;
            int r = id >> 2, kc = id & 3;
            const __nv_bfloat16* gk = kg + (size_t)(j0 + r) * DHEAD + kc * 8;
            unsigned dk = (unsigned)__cvta_generic_to_shared(&Ks[buf][r][kc * 8]);
            asm volatile("cp.async.cg.shared.global [%0], [%1], 16;\n" :: "r"(dk), "l"(gk));
            const __nv_bfloat16* gv = vg + (size_t)(j0 + r) * DHEAD + kc * 8;
            unsigned dv = (unsigned)__cvta_generic_to_shared(&Vs[buf][r][kc * 8]);
            asm volatile("cp.async.cg.shared.global [%0], [%1], 16;\n" :: "r"(dv), "l"(gv));
        }
        asm volatile("cp.async.commit_group;\n" ::: "memory");
    };

    loadKV(0, 0);

    unsigned qf[2][2][4];                 // [m-tile][kk][frag]
    float oacc[2][4][4] = {};             // [m-tile][nv][e]
    float lp[2][2] = {};                  // [m-tile][half]
    const int lr = lane >> 2, lc = (lane & 3) * 2;
    const float k1 = 0.17677669529663687f * LOG2E;
    const __nv_bfloat162 k2 = __float2bfloat162_rn(k1);
    const __nv_bfloat16* bp = bias8 + ((size_t)h << 20);

    int kbuf = 0;
    for (int t = 0; t < 16; t++) {
        if (t + 1 < 16) {
            int nb = kbuf + 1; if (nb == 3) nb = 0;
            loadKV(t + 1, nb);
            asm volatile("cp.async.wait_group 1;\n" ::: "memory");
        } else {
            asm volatile("cp.async.wait_group 0;\n" ::: "memory");
        }
        __syncthreads();

        if (t == 0) {
            #pragma unroll
            for (int mt = 0; mt < 2; mt++)
                #pragma unroll
                for (int kk = 0; kk < 2; kk++) {
                    unsigned ad = (unsigned)__cvta_generic_to_shared(
                        &Qs[w * 32 + mt * 16 + (lane & 15)][kk * 16 + (lane >> 4) * 8]);
                    asm volatile("ldmatrix.sync.aligned.m8n8.x4.shared.b16 {%0,%1,%2,%3}, [%4];"
                                 : "=r"(qf[mt][kk][0]), "=r"(qf[mt][kk][1]),
                                   "=r"(qf[mt][kk][2]), "=r"(qf[mt][kk][3]) : "r"(ad));
                }
        }

        // S phase: load K fragments ONCE, feed both m-tiles
        float sacc[2][8][4] = {};
        #pragma unroll
        for (int kk = 0; kk < 2; kk++) {
            unsigned bfr[8][2];
            #pragma unroll
            for (int np = 0; np < 4; np++) {
                int g = lane >> 3;
                unsigned ad = (unsigned)__cvta_generic_to_shared(
                    &Ks[kbuf][(np * 2 + (g >> 1)) * 8 + (lane & 7)][kk * 16 + (g & 1) * 8]);
                asm volatile("ldmatrix.sync.aligned.m8n8.x4.shared.b16 {%0,%1,%2,%3}, [%4];"
                             : "=r"(bfr[np * 2][0]), "=r"(bfr[np * 2][1]),
                               "=r"(bfr[np * 2 + 1][0]), "=r"(bfr[np * 2 + 1][1]) : "r"(ad));
            }
            #pragma unroll
            for (int mt = 0; mt < 2; mt++)
                #pragma unroll
                for (int nt = 0; nt < 8; nt++)
                    MMA16816(sacc[mt][nt], qf[mt][kk], bfr[nt][0], bfr[nt][1]);
        }

        // Softmax (bias loaded inline; MLP across 8 LDGs covers latency)
        unsigned pfr[2][8][2];
        #pragma unroll
        for (int mt = 0; mt < 2; mt++) {
            #pragma unroll
            for (int half = 0; half < 2; half++) {
                const __nv_bfloat16* brow =
                    bp + (size_t)(i0 + w * 32 + mt * 16 + lr + half * 8) * NPOS + t * 64;
                float rsum = 0.f;
                #pragma unroll
                for (int nt = 0; nt < 8; nt++) {
                    unsigned bb2 = *(const unsigned*)(brow + nt * 8 + lc);
                    __nv_bfloat162 bbv = *reinterpret_cast<__nv_bfloat162*>(&bb2);
                    __nv_bfloat162 s2 = __floats2bfloat162_rn(
                        sacc[mt][nt][half * 2 + 0], sacc[mt][nt][half * 2 + 1]);
                    __nv_bfloat162 arg = __hfma2(s2, k2, bbv);
                    unsigned argr = *reinterpret_cast<unsigned*>(&arg);
                    unsigned p2r;
                    asm("ex2.approx.ftz.bf16x2 %0, %1;" : "=r"(p2r) : "r"(argr));
                    pfr[mt][nt][half] = p2r;
                    float2 pf2 = __bfloat1622float2(
                        *reinterpret_cast<__nv_bfloat162*>(&p2r));
                    rsum += pf2.x + pf2.y;
                }
                lp[mt][half] += rsum;
            }
        }

        // PV phase: load V fragments ONCE, feed both m-tiles
        #pragma unroll
        for (int kc = 0; kc < 4; kc++) {
            unsigned bv[4][2];
            #pragma unroll
            for (int np = 0; np < 2; np++) {
                int quad = lane >> 3, rr = lane & 7;
                unsigned ad = (unsigned)__cvta_generic_to_shared(
                    &Vs[kbuf][kc * 16 + (quad & 1) * 8 + rr][np * 16 + (quad >> 1) * 8]);
                asm volatile("ldmatrix.sync.aligned.m8n8.x4.trans.shared.b16 {%0,%1,%2,%3}, [%4];"
                             : "=r"(bv[np * 2][0]), "=r"(bv[np * 2][1]),
                               "=r"(bv[np * 2 + 1][0]), "=r"(bv[np * 2 + 1][1]) : "r"(ad));
            }
            #pragma unroll
            for (int mt = 0; mt < 2; mt++) {
                unsigned pf[4];
                pf[0] = pfr[mt][2 * kc][0];
                pf[1] = pfr[mt][2 * kc][1];
                pf[2] = pfr[mt][2 * kc + 1][0];
                pf[3] = pfr[mt][2 * kc + 1][1];
                #pragma unroll
                for (int nv = 0; nv < 4; nv++)
                    MMA16816(oacc[mt][nv], pf, bv[nv][0], bv[nv][1]);
            }
        }

        kbuf++; if (kbuf == 3) kbuf = 0;
    }

    // Finalize
    #pragma unroll
    for (int mt = 0; mt < 2; mt++) {
        float inv[2];
        #pragma unroll
        for (int half = 0; half < 2; half++) {
            float l = lp[mt][half];
            l += __shfl_xor_sync(0xffffffffu, l, 1);
            l += __shfl_xor_sync(0xffffffffu, l, 2);
            inv[half] = 1.f / l;
        }
        #pragma unroll
        for (int half = 0; half < 2; half++) {
            int i = i0 + w * 32 + mt * 16 + lr + half * 8;
            __nv_bfloat16* orow = out + ((size_t)(b * NPOS + i)) * C_ + h * DHEAD;
            #pragma unroll
            for (int nv = 0; nv < 4; nv++) {
                __nv_bfloat162 pr = __floats2bfloat162_rn(
                    oacc[mt][nv][half * 2 + 0] * inv[half],
                    oacc[mt][nv][half * 2 + 1] * inv[half]);
                *(__nv_bfloat162*)&orow[nv * 8 + lc] = pr;
            }
        }
    }
}

// ---------------------------------------------------------------------------
// Host launch
// ---------------------------------------------------------------------------
extern "C" void kernel_launch(void* const* d_in, const int* in_sizes, int n_in,
                              void* d_out, int out_size)
{
    const float* x       = (const float*)d_in[0];
    const float* qkv_w   = (const float*)d_in[1];
    const float* proj_w  = (const float*)d_in[2];
    const float* proj_b  = (const float*)d_in[3];
    const float* ffn_w1  = (const float*)d_in[4];
    const float* ffn_b1  = (const float*)d_in[5];
    const float* ffn_w2  = (const float*)d_in[6];
    const float* ffn_b2  = (const float*)d_in[7];
    const float* n1w     = (const float*)d_in[8];
    const float* n1b     = (const float*)d_in[9];
    const float* n2w     = (const float*)d_in[10];
    const float* n2b     = (const float*)d_in[11];
    const float* btab    = (const float*)d_in[12];
    const int*   ridx    = (const int*)d_in[13];
    float* out = (float*)d_out;

    float* scratch = nullptr;
    cudaGetSymbolAddress((void**)&scratch, g_scratch);

    __nv_bfloat16* wb    = (__nv_bfloat16*)(scratch + OFF_WB);
    __nv_bfloat16* x1b   = (__nv_bfloat16*)(scratch + OFF_X1B);
    __nv_bfloat16* qkvb  = (__nv_bfloat16*)(scratch + OFF_QKVB);
    __nv_bfloat16* bias8 = (__nv_bfloat16*)(scratch + OFF_BIAS8);
    __nv_bfloat16* attnb = (__nv_bfloat16*)(scratch + OFF_ATTNB);
    float*         x3    = scratch + OFF_X3;
    __nv_bfloat16* x4b   = (__nv_bfloat16*)(scratch + OFF_X4B);
    __nv_bfloat16* h1b   = (__nv_bfloat16*)(scratch + OFF_H1B);

    static bool attrSet = false;
    if (!attrSet) {
        cudaFuncSetAttribute(proj_ln_kernel,
                             cudaFuncAttributeMaxDynamicSharedMemorySize, PSMEM_BYTES);
        attrSet = true;
    }

    // 0. Merged prep: weight conversion + bias precompute
    prep_kernel<<<7168, 256>>>(qkv_w, proj_w, ffn_w1, ffn_w2, wb, btab, ridx, bias8);

    // 1. LN1 (fused transpose)
    ln1_kernel<<<dim3(NPOS / 32, B_), 256>>>(x, n1w, n1b, x1b);

    // 2. QKV GEMM -> bf16 q/k/v head layout
    mma_gemm<0><<<dim3(768 / 128, NTOK / 128), 128>>>(
        x1b, wb + WB_QKV, NTOK, 768, C_, nullptr, nullptr, nullptr, qkvb);

    // 3. Flash attention (Q-tile 128, warp=32 rows, shared K/V fragments)
    attn_mma<<<dim3(NPOS / 128, HEADS, B_), 128>>>(qkvb, bias8, attnb);

    // 4. Fused proj GEMM + bias + residual(x) + LN2 -> x3 / x4b (64-row CTAs)
    proj_ln_kernel<<<NTOK / 64, 256, PSMEM_BYTES>>>(
        attnb, wb + WB_PROJ, proj_b, x, n2w, n2b, x3, x4b);

    // 5. FFN1 + GELU -> bf16 h1
    mma_gemm<2><<<dim3(HID / 128, NTOK / 128), 128>>>(
        x4b, wb + WB_W1, NTOK, HID, C_, ffn_b1, nullptr, nullptr, h1b);

    // 6. FFN2 + bias + residual(x3) -> fp32 output (B,C,H,W)
    mma_gemm<3><<<dim3(C_ / 128, NTOK / 128), 128>>>(
        h1b, wb + WB_W2, NTOK, C_, HID, ffn_b2, x3, out, nullptr);
}

// round 15
// speedup vs baseline: 1.1868x; 1.0534x over previous
#include <cuda_runtime.h>
#include <cuda_bf16.h>
#include <math.h>
#include <stdint.h>

// Problem constants
#define B_    16
#define C_    256
#define NTOK  16384
#define NPOS  1024
#define HEADS 8
#define DHEAD 32
#define HID   1024
#define LOG2E 1.4426950408889634f

// ---------------------------------------------------------------------------
// Scratch layout (float units)
// ---------------------------------------------------------------------------
#define OFF_WB     0u
#define WB_QKV     0u
#define WB_PROJ    196608u
#define WB_W1      262144u
#define WB_W2      524288u
#define WB_TOTAL   786432u

#define OFF_X1B    524288u
#define OFF_QKVB   2621440u
#define OFF_BIAS8  8912896u
#define OFF_ATTNB  13107200u
#define OFF_X3     15204352u
#define OFF_X4B    19398656u
#define OFF_H1B    21495808u
#define SCRATCH_FLOATS 33554432u

__device__ float g_scratch[SCRATCH_FLOATS];

// ---------------------------------------------------------------------------
// Merged prep.
// Blocks [0, 3072): weight fp32 -> bf16.
// Blocks [3072, 4096): bias precompute in FRAGMENT ORDER:
//   bias9[h][(ib*16+jb)][lane][k], k = half*16 + nt*2 + e, values pre-scaled
//   by log2e. Each lane's 32 values for one 16x64 (i-block, j-tile) are a
//   contiguous 64B run -> attention reads 2x LDG.128 per (mt, half).
// ---------------------------------------------------------------------------
__global__ __launch_bounds__(256)
void prep_kernel(const float* __restrict__ a, const float* __restrict__ b,
                 const float* __restrict__ c, const float* __restrict__ d,
                 __nv_bfloat16* __restrict__ wout,
                 const float* __restrict__ table, const int* __restrict__ ridx,
                 __nv_bfloat16* __restrict__ bias9)
{
    __shared__ __nv_bfloat16 vals[16][64][HEADS];   // 16 KB

    if (blockIdx.x < 3072) {
        unsigned i = blockIdx.x * 256u + threadIdx.x;
        if (i < WB_PROJ)            wout[i] = __float2bfloat16(a[i]);
        else if (i < WB_W1)         wout[i] = __float2bfloat16(b[i - WB_PROJ]);
        else if (i < WB_W2)         wout[i] = __float2bfloat16(c[i - WB_W1]);
        else if (i < WB_TOTAL)      wout[i] = __float2bfloat16(d[i - WB_W2]);
        return;
    }

    const int blk = blockIdx.x - 3072;      // 0..1023
    const int ib = blk >> 4;                // i-block 0..63 (16 rows each)
    const int jb = blk & 15;                // j-tile 0..15 (64 cols each)
    const int tid = threadIdx.x;

    // Gather: coalesced ridx rows, table gather (L1/L2 resident)
    #pragma unroll
    for (int it = 0; it < 4; it++) {
        int pos = it * 256 + tid;           // 0..1023
        int r = pos >> 6, cc = pos & 63;
        int idx = ridx[(size_t)(ib * 16 + r) * NPOS + jb * 64 + cc];
        const float* tr = table + (size_t)idx * HEADS;
        #pragma unroll
        for (int h = 0; h < HEADS; h++)
            vals[r][cc][h] = __float2bfloat16(tr[h] * LOG2E);
    }
    __syncthreads();

    // Scatter-free write: d contiguous across threads (coalesced), smem read
    #pragma unroll
    for (int h = 0; h < HEADS; h++) {
        #pragma unroll
        for (int it = 0; it < 4; it++) {
            int dd = it * 256 + tid;        // 0..1023
            int lane = dd >> 5, k = dd & 31;
            int half = k >> 4, nt = (k >> 1) & 7, e = k & 1;
            int r = half * 8 + (lane >> 2);
            int cc = nt * 8 + (lane & 3) * 2 + e;
            bias9[(size_t)h * 1048576u + (size_t)blk * 1024u + dd] = vals[r][cc][h];
        }
    }
}

// ---------------------------------------------------------------------------
// LN1: fused transpose LayerNorm (B,C,n) fp32 -> token-major bf16
// ---------------------------------------------------------------------------
__global__ __launch_bounds__(256)
void ln1_kernel(const float* __restrict__ in, const float* __restrict__ w,
                const float* __restrict__ bv, __nv_bfloat16* __restrict__ out)
{
    __shared__ float tile[C_][33];
    __shared__ float red1[8][32], red2[8][32];
    __shared__ float smu[32], srs[32];

    const int bb = blockIdx.y, p0 = blockIdx.x * 32;
    const int tid = threadIdx.x;

    #pragma unroll
    for (int it = 0; it < 32; it++) {
        int id = it * 256 + tid;
        int c = id >> 5, pp = id & 31;
        tile[c][pp] = in[((size_t)(bb * C_ + c)) * NPOS + p0 + pp];
    }
    __syncthreads();

    {
        int token = tid & 31, part = tid >> 5;
        float s1 = 0.f, s2 = 0.f;
        #pragma unroll
        for (int cc = 0; cc < 32; cc++) {
            float v = tile[part * 32 + cc][token];
            s1 += v; s2 += v * v;
        }
        red1[part][token] = s1;
        red2[part][token] = s2;
    }
    __syncthreads();
    if (tid < 32) {
        float t1 = 0.f, t2 = 0.f;
        #pragma unroll
        for (int p = 0; p < 8; p++) { t1 += red1[p][tid]; t2 += red2[p][tid]; }
        float mu  = t1 * (1.f / C_);
        float var = t2 * (1.f / C_) - mu * mu;
        smu[tid] = mu;
        srs[tid] = rsqrtf(var + 1e-5f);
    }
    __syncthreads();

    const float wc = w[tid], bc = bv[tid];
    #pragma unroll
    for (int it = 0; it < 32; it++) {
        float v = tile[tid][it];
        out[((size_t)(bb * NPOS + p0 + it)) * C_ + tid] =
            __float2bfloat16((v - smu[it]) * srs[it] * wc + bc);
    }
}

// ---------------------------------------------------------------------------
// bf16 mma.sync GEMM (128 thr / 4 warps, warp tile 64x64) — EPI 0/2/3
// ---------------------------------------------------------------------------
#define AKP 40
#define BNP 136

#define MMA16816(acc, af, b0, b1)                                              \
    asm volatile("mma.sync.aligned.m16n8k16.row.col.f32.bf16.bf16.f32 "        \
                 "{%0,%1,%2,%3}, {%4,%5,%6,%7}, {%8,%9}, {%0,%1,%2,%3};"       \
                 : "+f"(acc[0]), "+f"(acc[1]), "+f"(acc[2]), "+f"(acc[3])      \
                 : "r"(af[0]), "r"(af[1]), "r"(af[2]), "r"(af[3]),             \
                   "r"(b0), "r"(b1))

template<int EPI>
__global__ __launch_bounds__(128)
void mma_gemm(const __nv_bfloat16* __restrict__ A, const __nv_bfloat16* __restrict__ Bw,
              int M, int N, int K,
              const float* __restrict__ bias, const float* __restrict__ res,
              float* __restrict__ outf, __nv_bfloat16* __restrict__ outb)
{
    __shared__ __align__(16) __nv_bfloat16 As[3][128][AKP];
    __shared__ __align__(16) __nv_bfloat16 Bs[3][32][BNP];

    const int tid = threadIdx.x, lane = tid & 31, wid = tid >> 5;
    const int wm = wid >> 1, wn = wid & 1;
    const int m0 = blockIdx.y * 128, n0 = blockIdx.x * 128;

    float acc[4][8][4] = {};
    const int S = K >> 5;

    auto loadStage = [&](int s, int buf) {
        int kpos = s << 5;
        #pragma unroll
        for (int j = 0; j < 4; j++) {
            int id = tid + j * 128;
            int r = id >> 2, kc = id & 3;
            const __nv_bfloat16* g = A + (size_t)(m0 + r) * K + kpos + kc * 8;
            unsigned dst = (unsigned)__cvta_generic_to_shared(&As[buf][r][kc * 8]);
            asm volatile("cp.async.cg.shared.global [%0], [%1], 16;\n"
                         :: "r"(dst), "l"(g));
        }
        #pragma unroll
        for (int j = 0; j < 4; j++) {
            int id = tid + j * 128;
            int r = id >> 4, nc = id & 15;
            const __nv_bfloat16* g = Bw + (size_t)(kpos + r) * N + n0 + nc * 8;
            unsigned dst = (unsigned)__cvta_generic_to_shared(&Bs[buf][r][nc * 8]);
            asm volatile("cp.async.cg.shared.global [%0], [%1], 16;\n"
                         :: "r"(dst), "l"(g));
        }
        asm volatile("cp.async.commit_group;\n" ::: "memory");
    };

    loadStage(0, 0);
    loadStage(1, 1);

    int buf = 0;
    for (int s = 0; s < S; s++) {
        asm volatile("cp.async.wait_group 1;\n" ::: "memory");
        __syncthreads();
        if (s + 2 < S) {
            int nb = buf + 2; if (nb >= 3) nb -= 3;
            loadStage(s + 2, nb);
        }

        #pragma unroll
        for (int ks = 0; ks < 2; ks++) {
            const int kb = ks * 16;
            unsigned afr[4][4];
            #pragma unroll
            for (int mt = 0; mt < 4; mt++) {
                unsigned ad = (unsigned)__cvta_generic_to_shared(
                    &As[buf][wm * 64 + mt * 16 + (lane & 15)][kb + (lane >> 4) * 8]);
                asm volatile("ldmatrix.sync.aligned.m8n8.x4.shared.b16 {%0,%1,%2,%3}, [%4];"
                             : "=r"(afr[mt][0]), "=r"(afr[mt][1]),
                               "=r"(afr[mt][2]), "=r"(afr[mt][3]) : "r"(ad));
            }
            unsigned bfr[8][2];
            #pragma unroll
            for (int np = 0; np < 4; np++) {
                int quad = lane >> 3, rr = lane & 7;
                int row = kb + (quad & 1) * 8 + rr;
                int col = wn * 64 + np * 16 + (quad >> 1) * 8;
                unsigned bd = (unsigned)__cvta_generic_to_shared(&Bs[buf][row][col]);
                asm volatile("ldmatrix.sync.aligned.m8n8.x4.trans.shared.b16 {%0,%1,%2,%3}, [%4];"
                             : "=r"(bfr[np * 2][0]), "=r"(bfr[np * 2][1]),
                               "=r"(bfr[np * 2 + 1][0]), "=r"(bfr[np * 2 + 1][1]) : "r"(bd));
            }
            #pragma unroll
            for (int mt = 0; mt < 4; mt++)
                #pragma unroll
                for (int nt = 0; nt < 8; nt++)
                    MMA16816(acc[mt][nt], afr[mt], bfr[nt][0], bfr[nt][1]);
        }
        buf++; if (buf >= 3) buf = 0;
    }

    const int lr = lane >> 2, lc = (lane & 3) * 2;
    #pragma unroll
    for (int mt = 0; mt < 4; mt++) {
        #pragma unroll
        for (int half = 0; half < 2; half++) {
            int mrow = m0 + wm * 64 + mt * 16 + lr + half * 8;
            int bb = mrow >> 10, p = mrow & 1023;
            #pragma unroll
            for (int nt = 0; nt < 8; nt++) {
                if (EPI == 0) {
                    int c = n0 + wn * 64 + nt * 8 + lc;
                    int part = c >> 8, hh = (c >> 5) & 7, d = c & 31;
                    __nv_bfloat162 pr = __floats2bfloat162_rn(
                        acc[mt][nt][half * 2 + 0], acc[mt][nt][half * 2 + 1]);
                    *(__nv_bfloat162*)&outb[(size_t)part * 4194304u +
                        (((size_t)(bb * HEADS + hh)) * NPOS + p) * DHEAD + d] = pr;
                } else {
                    #pragma unroll
                    for (int e = 0; e < 2; e++) {
                        int c = n0 + wn * 64 + nt * 8 + lc + e;
                        float v = acc[mt][nt][half * 2 + e];
                        if (EPI == 2) {
                            float t = v + bias[c];
                            outb[(size_t)mrow * N + c] = __float2bfloat16(
                                0.5f * t * (1.f + erff(t * 0.70710678118654752f)));
                        } else {
                            outf[((size_t)(bb * C_ + c)) * NPOS + p] =
                                v + bias[c] + res[(size_t)mrow * C_ + c];
                        }
                    }
                }
            }
        }
    }
}

// ---------------------------------------------------------------------------
// Fused proj GEMM + bias + residual + LayerNorm2 (64-row CTAs, as R13)
// ---------------------------------------------------------------------------
#define PBNP 264
#define PA_STG (64 * AKP)
#define PB_STG (32 * PBNP)
#define PSMEM_BYTES ((3 * PA_STG + 3 * PB_STG) * 2)

__global__ __launch_bounds__(256)
void proj_ln_kernel(const __nv_bfloat16* __restrict__ A, const __nv_bfloat16* __restrict__ Bw,
                    const float* __restrict__ bias, const float* __restrict__ res,
                    const float* __restrict__ n2w, const float* __restrict__ n2b,
                    float* __restrict__ x3, __nv_bfloat16* __restrict__ x4b)
{
    extern __shared__ __align__(16) __nv_bfloat16 dsm[];
    __nv_bfloat16* AsBase = dsm;
    __nv_bfloat16* BsBase = dsm + 3 * PA_STG;
    __shared__ float sum4[4][64], sq4[4][64];
    __shared__ float smu[64], srs[64];

    const int tid = threadIdx.x, lane = tid & 31, wid = tid >> 5;
    const int wm = wid >> 2, wn = wid & 3;
    const int m0 = blockIdx.x * 64;
    const int K = C_, N = C_;

    float acc[2][8][4] = {};

    auto loadStage = [&](int s, int buf) {
        int kpos = s << 5;
        __nv_bfloat16* As = AsBase + buf * PA_STG;
        __nv_bfloat16* Bs = BsBase + buf * PB_STG;
        {
            int r = tid >> 2, kc = tid & 3;
            const __nv_bfloat16* g = A + (size_t)(m0 + r) * K + kpos + kc * 8;
            unsigned dst = (unsigned)__cvta_generic_to_shared(As + r * AKP + kc * 8);
            asm volatile("cp.async.cg.shared.global [%0], [%1], 16;\n" :: "r"(dst), "l"(g));
        }
        #pragma unroll
        for (int j = 0; j < 4; j++) {
            int id = tid + j * 256;
            int r = id >> 5, nc = id & 31;
            const __nv_bfloat16* g = Bw + (size_t)(kpos + r) * N + nc * 8;
            unsigned dst = (unsigned)__cvta_generic_to_shared(Bs + r * PBNP + nc * 8);
            asm volatile("cp.async.cg.shared.global [%0], [%1], 16;\n" :: "r"(dst), "l"(g));
        }
        asm volatile("cp.async.commit_group;\n" ::: "memory");
    };

    loadStage(0, 0);
    loadStage(1, 1);

    int buf = 0;
    const int S = K >> 5;
    for (int s = 0; s < S; s++) {
        asm volatile("cp.async.wait_group 1;\n" ::: "memory");
        __syncthreads();
        if (s + 2 < S) {
            int nb = buf + 2; if (nb >= 3) nb -= 3;
            loadStage(s + 2, nb);
        }
        __nv_bfloat16* As = AsBase + buf * PA_STG;
        __nv_bfloat16* Bs = BsBase + buf * PB_STG;

        #pragma unroll
        for (int ks = 0; ks < 2; ks++) {
            const int kb = ks * 16;
            unsigned afr[2][4];
            #pragma unroll
            for (int mt = 0; mt < 2; mt++) {
                unsigned ad = (unsigned)__cvta_generic_to_shared(
                    As + (wm * 32 + mt * 16 + (lane & 15)) * AKP + kb + (lane >> 4) * 8);
                asm volatile("ldmatrix.sync.aligned.m8n8.x4.shared.b16 {%0,%1,%2,%3}, [%4];"
                             : "=r"(afr[mt][0]), "=r"(afr[mt][1]),
                               "=r"(afr[mt][2]), "=r"(afr[mt][3]) : "r"(ad));
            }
            unsigned bfr[8][2];
            #pragma unroll
            for (int np = 0; np < 4; np++) {
                int quad = lane >> 3, rr = lane & 7;
                int row = kb + (quad & 1) * 8 + rr;
                int col = wn * 64 + np * 16 + (quad >> 1) * 8;
                unsigned bd = (unsigned)__cvta_generic_to_shared(Bs + row * PBNP + col);
                asm volatile("ldmatrix.sync.aligned.m8n8.x4.trans.shared.b16 {%0,%1,%2,%3}, [%4];"
                             : "=r"(bfr[np * 2][0]), "=r"(bfr[np * 2][1]),
                               "=r"(bfr[np * 2 + 1][0]), "=r"(bfr[np * 2 + 1][1]) : "r"(bd));
            }
            #pragma unroll
            for (int mt = 0; mt < 2; mt++)
                #pragma unroll
                for (int nt = 0; nt < 8; nt++)
                    MMA16816(acc[mt][nt], afr[mt], bfr[nt][0], bfr[nt][1]);
        }
        buf++; if (buf >= 3) buf = 0;
    }

    const int lr = lane >> 2, lc = (lane & 3) * 2;

    #pragma unroll
    for (int mt = 0; mt < 2; mt++) {
        #pragma unroll
        for (int half = 0; half < 2; half++) {
            int mrow = m0 + wm * 32 + mt * 16 + lr + half * 8;
            int bb = mrow >> 10, p = mrow & 1023;
            float s1 = 0.f, s2 = 0.f;
            #pragma unroll
            for (int nt = 0; nt < 8; nt++) {
                #pragma unroll
                for (int e = 0; e < 2; e++) {
                    int c = wn * 64 + nt * 8 + lc + e;
                    float t = acc[mt][nt][half * 2 + e] + bias[c] +
                              res[((size_t)(bb * C_ + c)) * NPOS + p];
                    acc[mt][nt][half * 2 + e] = t;
                    s1 += t; s2 += t * t;
                }
            }
            s1 += __shfl_xor_sync(0xffffffffu, s1, 1);
            s2 += __shfl_xor_sync(0xffffffffu, s2, 1);
            s1 += __shfl_xor_sync(0xffffffffu, s1, 2);
            s2 += __shfl_xor_sync(0xffffffffu, s2, 2);
            if ((lane & 3) == 0) {
                int r = wm * 32 + mt * 16 + lr + half * 8;
                sum4[wn][r] = s1;
                sq4[wn][r] = s2;
            }
        }
    }
    __syncthreads();
    if (tid < 64) {
        float t1 = sum4[0][tid] + sum4[1][tid] + sum4[2][tid] + sum4[3][tid];
        float t2 = sq4[0][tid] + sq4[1][tid] + sq4[2][tid] + sq4[3][tid];
        float mu  = t1 * (1.f / C_);
        float var = t2 * (1.f / C_) - mu * mu;
        smu[tid] = mu;
        srs[tid] = rsqrtf(var + 1e-5f);
    }
    __syncthreads();

    #pragma unroll
    for (int mt = 0; mt < 2; mt++) {
        #pragma unroll
        for (int half = 0; half < 2; half++) {
            int r = wm * 32 + mt * 16 + lr + half * 8;
            int mrow = m0 + r;
            float mu = smu[r], rs = srs[r];
            #pragma unroll
            for (int nt = 0; nt < 8; nt++) {
                int c = wn * 64 + nt * 8 + lc;
                float t0 = acc[mt][nt][half * 2 + 0];
                float t1v = acc[mt][nt][half * 2 + 1];
                *(float2*)&x3[(size_t)mrow * C_ + c] = make_float2(t0, t1v);
                float g0 = (t0 - mu) * rs * n2w[c] + n2b[c];
                float g1 = (t1v - mu) * rs * n2w[c + 1] + n2b[c + 1];
                __nv_bfloat162 pr = __floats2bfloat162_rn(g0, g1);
                *(__nv_bfloat162*)&x4b[(size_t)mrow * C_ + c] = pr;
            }
        }
    }
}

// ---------------------------------------------------------------------------
// Tensor-core flash attention — Q-tile 128 / CTA, 128 thr / 4 warps,
// warp = 32 q-rows (2 m-tiles), K/V fragments shared across m-tiles.
// Bias read from fragment-ordered bias9 via 2x LDG.128 per (mt, half).
// ---------------------------------------------------------------------------
__global__ __launch_bounds__(128, 3)
void attn_mma(const __nv_bfloat16* __restrict__ qkv,
              const __nv_bfloat16* __restrict__ bias9,
              __nv_bfloat16* __restrict__ out)
{
    __shared__ __align__(16) __nv_bfloat16 Qs[128][40];
    __shared__ __align__(16) __nv_bfloat16 Ks[3][64][40];
    __shared__ __align__(16) __nv_bfloat16 Vs[3][64][40];

    const int tid = threadIdx.x, lane = tid & 31, w = tid >> 5;
    const int qt = blockIdx.x, h = blockIdx.y, b = blockIdx.z;
    const int i0 = qt * 128;
    const size_t headBase = ((size_t)(b * HEADS + h)) * NPOS * DHEAD;
    const __nv_bfloat16* qg = qkv + headBase;
    const __nv_bfloat16* kg = qkv + 4194304u + headBase;
    const __nv_bfloat16* vg = qkv + 8388608u + headBase;

    // Q tile (128 rows) -> smem
    {
        int id = tid;
        #pragma unroll
        for (int it = 0; it < 4; it++, id += 128) {
            int r = id >> 2, kc = id & 3;
            const __nv_bfloat16* g = qg + (size_t)(i0 + r) * DHEAD + kc * 8;
            unsigned dst = (unsigned)__cvta_generic_to_shared(&Qs[r][kc * 8]);
            asm volatile("cp.async.cg.shared.global [%0], [%1], 16;\n" :: "r"(dst), "l"(g));
        }
        asm volatile("cp.async.commit_group;\n" ::: "memory");
    }

    auto loadKV = [&](int t, int buf) {
        int j0 = t * 64;
        #pragma unroll
        for (int it = 0; it < 2; it++) {
            int id = tid + it * 128;
            int r = id >> 2, kc = id & 3;
            const __nv_bfloat16* gk = kg + (size_t)(j0 + r) * DHEAD + kc * 8;
            unsigned dk = (unsigned)__cvta_generic_to_shared(&Ks[buf][r][kc * 8]);
            asm volatile("cp.async.cg.shared.global [%0], [%1], 16;\n" :: "r"(dk), "l"(gk));
            const __nv_bfloat16* gv = vg + (size_t)(j0 + r) * DHEAD + kc * 8;
            unsigned dv = (unsigned)__cvta_generic_to_shared(&Vs[buf][r][kc * 8]);
            asm volatile("cp.async.cg.shared.global [%0], [%1], 16;\n" :: "r"(dv), "l"(gv));
        }
        asm volatile("cp.async.commit_group;\n" ::: "memory");
    };

    loadKV(0, 0);

    unsigned qf[2][2][4];
    float oacc[2][4][4] = {};
    float lp[2][2] = {};
    const int lr = lane >> 2, lc = (lane & 3) * 2;
    const float k1 = 0.17677669529663687f * LOG2E;
    const __nv_bfloat162 k2 = __float2bfloat162_rn(k1);
    // Fragment-ordered bias base for this (head, lane); per (mt, tile):
    //   block = ((qt*8 + w*2 + mt) * 16 + t), offset block*1024 + lane*32
    const __nv_bfloat16* bb0 = bias9 + ((size_t)h << 20) + lane * 32;

    int kbuf = 0;
    for (int t = 0; t < 16; t++) {
        if (t + 1 < 16) {
            int nb = kbuf + 1; if (nb == 3) nb = 0;
            loadKV(t + 1, nb);
            asm volatile("cp.async.wait_group 1;\n" ::: "memory");
        } else {
            asm volatile("cp.async.wait_group 0;\n" ::: "memory");
        }
        __syncthreads();

        if (t == 0) {
            #pragma unroll
            for (int mt = 0; mt < 2; mt++)
                #pragma unroll
                for (int kk = 0; kk < 2; kk++) {
                    unsigned ad = (unsigned)__cvta_generic_to_shared(
                        &Qs[w * 32 + mt * 16 + (lane & 15)][kk * 16 + (lane >> 4) * 8]);
                    asm volatile("ldmatrix.sync.aligned.m8n8.x4.shared.b16 {%0,%1,%2,%3}, [%4];"
                                 : "=r"(qf[mt][kk][0]), "=r"(qf[mt][kk][1]),
                                   "=r"(qf[mt][kk][2]), "=r"(qf[mt][kk][3]) : "r"(ad));
                }
        }

        // S phase: K fragments loaded once, feed both m-tiles
        float sacc[2][8][4] = {};
        #pragma unroll
        for (int kk = 0; kk < 2; kk++) {
            unsigned bfr[8][2];
            #pragma unroll
            for (int np = 0; np < 4; np++) {
                int g = lane >> 3;
                unsigned ad = (unsigned)__cvta_generic_to_shared(
                    &Ks[kbuf][(np * 2 + (g >> 1)) * 8 + (lane & 7)][kk * 16 + (g & 1) * 8]);
                asm volatile("ldmatrix.sync.aligned.m8n8.x4.shared.b16 {%0,%1,%2,%3}, [%4];"
                             : "=r"(bfr[np * 2][0]), "=r"(bfr[np * 2][1]),
                               "=r"(bfr[np * 2 + 1][0]), "=r"(bfr[np * 2 + 1][1]) : "r"(ad));
            }
            #pragma unroll
            for (int mt = 0; mt < 2; mt++)
                #pragma unroll
                for (int nt = 0; nt < 8; nt++)
                    MMA16816(sacc[mt][nt], qf[mt][kk], bfr[nt][0], bfr[nt][1]);
        }

        // Softmax: bias via vectorized fragment-order loads
        unsigned pfr[2][8][2];
        #pragma unroll
        for (int mt = 0; mt < 2; mt++) {
            const __nv_bfloat16* bl =
                bb0 + (size_t)(((qt * 8 + w * 2 + mt) * 16 + t)) * 1024u;
            #pragma unroll
            for (int half = 0; half < 2; half++) {
                uint4 v0 = *(const uint4*)(bl + half * 16);
                uint4 v1 = *(const uint4*)(bl + half * 16 + 8);
                unsigned wv[8] = {v0.x, v0.y, v0.z, v0.w, v1.x, v1.y, v1.z, v1.w};
                float rsum = 0.f;
                #pragma unroll
                for (int nt = 0; nt < 8; nt++) {
                    __nv_bfloat162 bbv = *reinterpret_cast<__nv_bfloat162*>(&wv[nt]);
                    __nv_bfloat162 s2 = __floats2bfloat162_rn(
                        sacc[mt][nt][half * 2 + 0], sacc[mt][nt][half * 2 + 1]);
                    __nv_bfloat162 arg = __hfma2(s2, k2, bbv);
                    unsigned argr = *reinterpret_cast<unsigned*>(&arg);
                    unsigned p2r;
                    asm("ex2.approx.ftz.bf16x2 %0, %1;" : "=r"(p2r) : "r"(argr));
                    pfr[mt][nt][half] = p2r;
                    float2 pf2 = __bfloat1622float2(
                        *reinterpret_cast<__nv_bfloat162*>(&p2r));
                    rsum += pf2.x + pf2.y;
                }
                lp[mt][half] += rsum;
            }
        }

        // PV phase: V fragments loaded once, feed both m-tiles
        #pragma unroll
        for (int kc = 0; kc < 4; kc++) {
            unsigned bv[4][2];
            #pragma unroll
            for (int np = 0; np < 2; np++) {
                int quad = lane >> 3, rr = lane & 7;
                unsigned ad = (unsigned)__cvta_generic_to_shared(
                    &Vs[kbuf][kc * 16 + (quad & 1) * 8 + rr][np * 16 + (quad >> 1) * 8]);
                asm volatile("ldmatrix.sync.aligned.m8n8.x4.trans.shared.b16 {%0,%1,%2,%3}, [%4];"
                             : "=r"(bv[np * 2][0]), "=r"(bv[np * 2][1]),
                               "=r"(bv[np * 2 + 1][0]), "=r"(bv[np * 2 + 1][1]) : "r"(ad));
            }
            #pragma unroll
            for (int mt = 0; mt < 2; mt++) {
                unsigned pf[4];
                pf[0] = pfr[mt][2 * kc][0];
                pf[1] = pfr[mt][2 * kc][1];
                pf[2] = pfr[mt][2 * kc + 1][0];
                pf[3] = pfr[mt][2 * kc + 1][1];
                #pragma unroll
                for (int nv = 0; nv < 4; nv++)
                    MMA16816(oacc[mt][nv], pf, bv[nv][0], bv[nv][1]);
            }
        }

        kbuf++; if (kbuf == 3) kbuf = 0;
    }

    // Finalize
    #pragma unroll
    for (int mt = 0; mt < 2; mt++) {
        float inv[2];
        #pragma unroll
        for (int half = 0; half < 2; half++) {
            float l = lp[mt][half];
            l += __shfl_xor_sync(0xffffffffu, l, 1);
            l += __shfl_xor_sync(0xffffffffu, l, 2);
            inv[half] = 1.f / l;
        }
        #pragma unroll
        for (int half = 0; half < 2; half++) {
            int i = i0 + w * 32 + mt * 16 + lr + half * 8;
            __nv_bfloat16* orow = out + ((size_t)(b * NPOS + i)) * C_ + h * DHEAD;
            #pragma unroll
            for (int nv = 0; nv < 4; nv++) {
                __nv_bfloat162 pr = __floats2bfloat162_rn(
                    oacc[mt][nv][half * 2 + 0] * inv[half],
                    oacc[mt][nv][half * 2 + 1] * inv[half]);
                *(__nv_bfloat162*)&orow[nv * 8 + lc] = pr;
            }
        }
    }
}

// ---------------------------------------------------------------------------
// Host launch
// ---------------------------------------------------------------------------
extern "C" void kernel_launch(void* const* d_in, const int* in_sizes, int n_in,
                              void* d_out, int out_size)
{
    const float* x       = (const float*)d_in[0];
    const float* qkv_w   = (const float*)d_in[1];
    const float* proj_w  = (const float*)d_in[2];
    const float* proj_b  = (const float*)d_in[3];
    const float* ffn_w1  = (const float*)d_in[4];
    const float* ffn_b1  = (const float*)d_in[5];
    const float* ffn_w2  = (const float*)d_in[6];
    const float* ffn_b2  = (const float*)d_in[7];
    const float* n1w     = (const float*)d_in[8];
    const float* n1b     = (const float*)d_in[9];
    const float* n2w     = (const float*)d_in[10];
    const float* n2b     = (const float*)d_in[11];
    const float* btab    = (const float*)d_in[12];
    const int*   ridx    = (const int*)d_in[13];
    float* out = (float*)d_out;

    float* scratch = nullptr;
    cudaGetSymbolAddress((void**)&scratch, g_scratch);

    __nv_bfloat16* wb    = (__nv_bfloat16*)(scratch + OFF_WB);
    __nv_bfloat16* x1b   = (__nv_bfloat16*)(scratch + OFF_X1B);
    __nv_bfloat16* qkvb  = (__nv_bfloat16*)(scratch + OFF_QKVB);
    __nv_bfloat16* bias9 = (__nv_bfloat16*)(scratch + OFF_BIAS8);
    __nv_bfloat16* attnb = (__nv_bfloat16*)(scratch + OFF_ATTNB);
    float*         x3    = scratch + OFF_X3;
    __nv_bfloat16* x4b   = (__nv_bfloat16*)(scratch + OFF_X4B);
    __nv_bfloat16* h1b   = (__nv_bfloat16*)(scratch + OFF_H1B);

    static bool attrSet = false;
    if (!attrSet) {
        cudaFuncSetAttribute(proj_ln_kernel,
                             cudaFuncAttributeMaxDynamicSharedMemorySize, PSMEM_BYTES);
        attrSet = true;
    }

    // 0. Merged prep: weight conversion + fragment-ordered bias precompute
    prep_kernel<<<4096, 256>>>(qkv_w, proj_w, ffn_w1, ffn_w2, wb, btab, ridx, bias9);

    // 1. LN1 (fused transpose)
    ln1_kernel<<<dim3(NPOS / 32, B_), 256>>>(x, n1w, n1b, x1b);

    // 2. QKV GEMM -> bf16 q/k/v head layout
    mma_gemm<0><<<dim3(768 / 128, NTOK / 128), 128>>>(
        x1b, wb + WB_QKV, NTOK, 768, C_, nullptr, nullptr, nullptr, qkvb);

    // 3. Flash attention (Q-tile 128, shared K/V fragments, vectorized bias)
    attn_mma<<<dim3(NPOS / 128, HEADS, B_), 128>>>(qkvb, bias9, attnb);

    // 4. Fused proj GEMM + bias + residual(x) + LN2 -> x3 / x4b (64-row CTAs)
    proj_ln_kernel<<<NTOK / 64, 256, PSMEM_BYTES>>>(
        attnb, wb + WB_PROJ, proj_b, x, n2w, n2b, x3, x4b);

    // 5. FFN1 + GELU -> bf16 h1
    mma_gemm<2><<<dim3(HID / 128, NTOK / 128), 128>>>(
        x4b, wb + WB_W1, NTOK, HID, C_, ffn_b1, nullptr, nullptr, h1b);

    // 6. FFN2 + bias + residual(x3) -> fp32 output (B,C,H,W)
    mma_gemm<3><<<dim3(C_ / 128, NTOK / 128), 128>>>(
        h1b, wb + WB_W2, NTOK, C_, HID, ffn_b2, x3, out, nullptr);
}

// round 16
// speedup vs baseline: 1.2187x; 1.0269x over previous
#include <cuda_runtime.h>
#include <cuda_bf16.h>
#include <math.h>
#include <stdint.h>

// Problem constants
#define B_    16
#define C_    256
#define NTOK  16384
#define NPOS  1024
#define HEADS 8
#define DHEAD 32
#define HID   1024
#define LOG2E 1.4426950408889634f

// ---------------------------------------------------------------------------
// Scratch layout (float units)
// ---------------------------------------------------------------------------
#define OFF_WB     0u
#define WB_QKV     0u
#define WB_PROJ    196608u
#define WB_W1      262144u
#define WB_W2      524288u
#define WB_TOTAL   786432u

#define OFF_X1B    524288u
#define OFF_QKVB   2621440u
#define OFF_BIAS8  8912896u
#define OFF_ATTNB  13107200u
#define OFF_X3     15204352u
#define OFF_X4B    19398656u
#define OFF_H1B    21495808u
#define SCRATCH_FLOATS 33554432u

__device__ float g_scratch[SCRATCH_FLOATS];

// ---------------------------------------------------------------------------
// Merged prep.
// Blocks [0, 3072): weight fp32 -> bf16.
// Blocks [3072, 4096): bias precompute, QUARTER-ordered fragment layout:
//   block (ib*16+jb) of 1024 halves laid out as [q][lane][j]:
//   offset = q*256 + lane*8 + j, where k = q*8 + j (k = half*16 + nt*2 + e).
//   Each warp uint4 load of one quarter = 512B contiguous = 4 L1 wavefronts.
// ---------------------------------------------------------------------------
__global__ __launch_bounds__(256)
void prep_kernel(const float* __restrict__ a, const float* __restrict__ b,
                 const float* __restrict__ c, const float* __restrict__ d,
                 __nv_bfloat16* __restrict__ wout,
                 const float* __restrict__ table, const int* __restrict__ ridx,
                 __nv_bfloat16* __restrict__ bias9)
{
    __shared__ __nv_bfloat16 vals[16][64][HEADS];   // 16 KB

    if (blockIdx.x < 3072) {
        unsigned i = blockIdx.x * 256u + threadIdx.x;
        if (i < WB_PROJ)            wout[i] = __float2bfloat16(a[i]);
        else if (i < WB_W1)         wout[i] = __float2bfloat16(b[i - WB_PROJ]);
        else if (i < WB_W2)         wout[i] = __float2bfloat16(c[i - WB_W1]);
        else if (i < WB_TOTAL)      wout[i] = __float2bfloat16(d[i - WB_W2]);
        return;
    }

    const int blk = blockIdx.x - 3072;      // 0..1023
    const int ib = blk >> 4;                // i-block 0..63 (16 rows each)
    const int jb = blk & 15;                // j-tile 0..15 (64 cols each)
    const int tid = threadIdx.x;

    // Gather: coalesced ridx rows, table gather (L2 resident)
    #pragma unroll
    for (int it = 0; it < 4; it++) {
        int pos = it * 256 + tid;           // 0..1023
        int r = pos >> 6, cc = pos & 63;
        int idx = ridx[(size_t)(ib * 16 + r) * NPOS + jb * 64 + cc];
        const float* tr = table + (size_t)idx * HEADS;
        #pragma unroll
        for (int h = 0; h < HEADS; h++)
            vals[r][cc][h] = __float2bfloat16(tr[h] * LOG2E);
    }
    __syncthreads();

    // Quarter-ordered write (coalesced across threads)
    #pragma unroll
    for (int h = 0; h < HEADS; h++) {
        #pragma unroll
        for (int it = 0; it < 4; it++) {
            int dd = it * 256 + tid;        // 0..1023
            int q = dd >> 8, rem = dd & 255;
            int lane = rem >> 3, j = rem & 7;
            int k = q * 8 + j;
            int half = k >> 4, nt = (k >> 1) & 7, e = k & 1;
            int r = half * 8 + (lane >> 2);
            int cc = nt * 8 + (lane & 3) * 2 + e;
            bias9[(size_t)h * 1048576u + (size_t)blk * 1024u + dd] = vals[r][cc][h];
        }
    }
}

// ---------------------------------------------------------------------------
// LN1: fused transpose LayerNorm (B,C,n) fp32 -> token-major bf16
// ---------------------------------------------------------------------------
__global__ __launch_bounds__(256)
void ln1_kernel(const float* __restrict__ in, const float* __restrict__ w,
                const float* __restrict__ bv, __nv_bfloat16* __restrict__ out)
{
    __shared__ float tile[C_][33];
    __shared__ float red1[8][32], red2[8][32];
    __shared__ float smu[32], srs[32];

    const int bb = blockIdx.y, p0 = blockIdx.x * 32;
    const int tid = threadIdx.x;

    #pragma unroll
    for (int it = 0; it < 32; it++) {
        int id = it * 256 + tid;
        int c = id >> 5, pp = id & 31;
        tile[c][pp] = in[((size_t)(bb * C_ + c)) * NPOS + p0 + pp];
    }
    __syncthreads();

    {
        int token = tid & 31, part = tid >> 5;
        float s1 = 0.f, s2 = 0.f;
        #pragma unroll
        for (int cc = 0; cc < 32; cc++) {
            float v = tile[part * 32 + cc][token];
            s1 += v; s2 += v * v;
        }
        red1[part][token] = s1;
        red2[part][token] = s2;
    }
    __syncthreads();
    if (tid < 32) {
        float t1 = 0.f, t2 = 0.f;
        #pragma unroll
        for (int p = 0; p < 8; p++) { t1 += red1[p][tid]; t2 += red2[p][tid]; }
        float mu  = t1 * (1.f / C_);
        float var = t2 * (1.f / C_) - mu * mu;
        smu[tid] = mu;
        srs[tid] = rsqrtf(var + 1e-5f);
    }
    __syncthreads();

    const float wc = w[tid], bc = bv[tid];
    #pragma unroll
    for (int it = 0; it < 32; it++) {
        float v = tile[tid][it];
        out[((size_t)(bb * NPOS + p0 + it)) * C_ + tid] =
            __float2bfloat16((v - smu[it]) * srs[it] * wc + bc);
    }
}

// ---------------------------------------------------------------------------
// bf16 mma.sync GEMM (128 thr / 4 warps, warp tile 64x64) — EPI 0/2/3
// ---------------------------------------------------------------------------
#define AKP 40
#define BNP 136

#define MMA16816(acc, af, b0, b1)                                              \
    asm volatile("mma.sync.aligned.m16n8k16.row.col.f32.bf16.bf16.f32 "        \
                 "{%0,%1,%2,%3}, {%4,%5,%6,%7}, {%8,%9}, {%0,%1,%2,%3};"       \
                 : "+f"(acc[0]), "+f"(acc[1]), "+f"(acc[2]), "+f"(acc[3])      \
                 : "r"(af[0]), "r"(af[1]), "r"(af[2]), "r"(af[3]),             \
                   "r"(b0), "r"(b1))

template<int EPI>
__global__ __launch_bounds__(128)
void mma_gemm(const __nv_bfloat16* __restrict__ A, const __nv_bfloat16* __restrict__ Bw,
              int M, int N, int K,
              const float* __restrict__ bias, const float* __restrict__ res,
              float* __restrict__ outf, __nv_bfloat16* __restrict__ outb)
{
    __shared__ __align__(16) __nv_bfloat16 As[3][128][AKP];
    __shared__ __align__(16) __nv_bfloat16 Bs[3][32][BNP];

    const int tid = threadIdx.x, lane = tid & 31, wid = tid >> 5;
    const int wm = wid >> 1, wn = wid & 1;
    const int m0 = blockIdx.y * 128, n0 = blockIdx.x * 128;

    float acc[4][8][4] = {};
    const int S = K >> 5;

    auto loadStage = [&](int s, int buf) {
        int kpos = s << 5;
        #pragma unroll
        for (int j = 0; j < 4; j++) {
            int id = tid + j * 128;
            int r = id >> 2, kc = id & 3;
            const __nv_bfloat16* g = A + (size_t)(m0 + r) * K + kpos + kc * 8;
            unsigned dst = (unsigned)__cvta_generic_to_shared(&As[buf][r][kc * 8]);
            asm volatile("cp.async.cg.shared.global [%0], [%1], 16;\n"
                         :: "r"(dst), "l"(g));
        }
        #pragma unroll
        for (int j = 0; j < 4; j++) {
            int id = tid + j * 128;
            int r = id >> 4, nc = id & 15;
            const __nv_bfloat16* g = Bw + (size_t)(kpos + r) * N + n0 + nc * 8;
            unsigned dst = (unsigned)__cvta_generic_to_shared(&Bs[buf][r][nc * 8]);
            asm volatile("cp.async.cg.shared.global [%0], [%1], 16;\n"
                         :: "r"(dst), "l"(g));
        }
        asm volatile("cp.async.commit_group;\n" ::: "memory");
    };

    loadStage(0, 0);
    loadStage(1, 1);

    int buf = 0;
    for (int s = 0; s < S; s++) {
        asm volatile("cp.async.wait_group 1;\n" ::: "memory");
        __syncthreads();
        if (s + 2 < S) {
            int nb = buf + 2; if (nb >= 3) nb -= 3;
            loadStage(s + 2, nb);
        }

        #pragma unroll
        for (int ks = 0; ks < 2; ks++) {
            const int kb = ks * 16;
            unsigned afr[4][4];
            #pragma unroll
            for (int mt = 0; mt < 4; mt++) {
                unsigned ad = (unsigned)__cvta_generic_to_shared(
                    &As[buf][wm * 64 + mt * 16 + (lane & 15)][kb + (lane >> 4) * 8]);
                asm volatile("ldmatrix.sync.aligned.m8n8.x4.shared.b16 {%0,%1,%2,%3}, [%4];"
                             : "=r"(afr[mt][0]), "=r"(afr[mt][1]),
                               "=r"(afr[mt][2]), "=r"(afr[mt][3]) : "r"(ad));
            }
            unsigned bfr[8][2];
            #pragma unroll
            for (int np = 0; np < 4; np++) {
                int quad = lane >> 3, rr = lane & 7;
                int row = kb + (quad & 1) * 8 + rr;
                int col = wn * 64 + np * 16 + (quad >> 1) * 8;
                unsigned bd = (unsigned)__cvta_generic_to_shared(&Bs[buf][row][col]);
                asm volatile("ldmatrix.sync.aligned.m8n8.x4.trans.shared.b16 {%0,%1,%2,%3}, [%4];"
                             : "=r"(bfr[np * 2][0]), "=r"(bfr[np * 2][1]),
                               "=r"(bfr[np * 2 + 1][0]), "=r"(bfr[np * 2 + 1][1]) : "r"(bd));
            }
            #pragma unroll
            for (int mt = 0; mt < 4; mt++)
                #pragma unroll
                for (int nt = 0; nt < 8; nt++)
                    MMA16816(acc[mt][nt], afr[mt], bfr[nt][0], bfr[nt][1]);
        }
        buf++; if (buf >= 3) buf = 0;
    }

    const int lr = lane >> 2, lc = (lane & 3) * 2;
    #pragma unroll
    for (int mt = 0; mt < 4; mt++) {
        #pragma unroll
        for (int half = 0; half < 2; half++) {
            int mrow = m0 + wm * 64 + mt * 16 + lr + half * 8;
            int bb = mrow >> 10, p = mrow & 1023;
            #pragma unroll
            for (int nt = 0; nt < 8; nt++) {
                if (EPI == 0) {
                    int c = n0 + wn * 64 + nt * 8 + lc;
                    int part = c >> 8, hh = (c >> 5) & 7, d = c & 31;
                    __nv_bfloat162 pr = __floats2bfloat162_rn(
                        acc[mt][nt][half * 2 + 0], acc[mt][nt][half * 2 + 1]);
                    *(__nv_bfloat162*)&outb[(size_t)part * 4194304u +
                        (((size_t)(bb * HEADS + hh)) * NPOS + p) * DHEAD + d] = pr;
                } else {
                    #pragma unroll
                    for (int e = 0; e < 2; e++) {
                        int c = n0 + wn * 64 + nt * 8 + lc + e;
                        float v = acc[mt][nt][half * 2 + e];
                        if (EPI == 2) {
                            float t = v + bias[c];
                            outb[(size_t)mrow * N + c] = __float2bfloat16(
                                0.5f * t * (1.f + erff(t * 0.70710678118654752f)));
                        } else {
                            outf[((size_t)(bb * C_ + c)) * NPOS + p] =
                                v + bias[c] + res[(size_t)mrow * C_ + c];
                        }
                    }
                }
            }
        }
    }
}

// ---------------------------------------------------------------------------
// Fused proj GEMM + bias + residual + LayerNorm2 (64-row CTAs)
// ---------------------------------------------------------------------------
#define PBNP 264
#define PA_STG (64 * AKP)
#define PB_STG (32 * PBNP)
#define PSMEM_BYTES ((3 * PA_STG + 3 * PB_STG) * 2)

__global__ __launch_bounds__(256)
void proj_ln_kernel(const __nv_bfloat16* __restrict__ A, const __nv_bfloat16* __restrict__ Bw,
                    const float* __restrict__ bias, const float* __restrict__ res,
                    const float* __restrict__ n2w, const float* __restrict__ n2b,
                    float* __restrict__ x3, __nv_bfloat16* __restrict__ x4b)
{
    extern __shared__ __align__(16) __nv_bfloat16 dsm[];
    __nv_bfloat16* AsBase = dsm;
    __nv_bfloat16* BsBase = dsm + 3 * PA_STG;
    __shared__ float sum4[4][64], sq4[4][64];
    __shared__ float smu[64], srs[64];

    const int tid = threadIdx.x, lane = tid & 31, wid = tid >> 5;
    const int wm = wid >> 2, wn = wid & 3;
    const int m0 = blockIdx.x * 64;
    const int K = C_, N = C_;

    float acc[2][8][4] = {};

    auto loadStage = [&](int s, int buf) {
        int kpos = s << 5;
        __nv_bfloat16* As = AsBase + buf * PA_STG;
        __nv_bfloat16* Bs = BsBase + buf * PB_STG;
        {
            int r = tid >> 2, kc = tid & 3;
            const __nv_bfloat16* g = A + (size_t)(m0 + r) * K + kpos + kc * 8;
            unsigned dst = (unsigned)__cvta_generic_to_shared(As + r * AKP + kc * 8);
            asm volatile("cp.async.cg.shared.global [%0], [%1], 16;\n" :: "r"(dst), "l"(g));
        }
        #pragma unroll
        for (int j = 0; j < 4; j++) {
            int id = tid + j * 256;
            int r = id >> 5, nc = id & 31;
            const __nv_bfloat16* g = Bw + (size_t)(kpos + r) * N + nc * 8;
            unsigned dst = (unsigned)__cvta_generic_to_shared(Bs + r * PBNP + nc * 8);
            asm volatile("cp.async.cg.shared.global [%0], [%1], 16;\n" :: "r"(dst), "l"(g));
        }
        asm volatile("cp.async.commit_group;\n" ::: "memory");
    };

    loadStage(0, 0);
    loadStage(1, 1);

    int buf = 0;
    const int S = K >> 5;
    for (int s = 0; s < S; s++) {
        asm volatile("cp.async.wait_group 1;\n" ::: "memory");
        __syncthreads();
        if (s + 2 < S) {
            int nb = buf + 2; if (nb >= 3) nb -= 3;
            loadStage(s + 2, nb);
        }
        __nv_bfloat16* As = AsBase + buf * PA_STG;
        __nv_bfloat16* Bs = BsBase + buf * PB_STG;

        #pragma unroll
        for (int ks = 0; ks < 2; ks++) {
            const int kb = ks * 16;
            unsigned afr[2][4];
            #pragma unroll
            for (int mt = 0; mt < 2; mt++) {
                unsigned ad = (unsigned)__cvta_generic_to_shared(
                    As + (wm * 32 + mt * 16 + (lane & 15)) * AKP + kb + (lane >> 4) * 8);
                asm volatile("ldmatrix.sync.aligned.m8n8.x4.shared.b16 {%0,%1,%2,%3}, [%4];"
                             : "=r"(afr[mt][0]), "=r"(afr[mt][1]),
                               "=r"(afr[mt][2]), "=r"(afr[mt][3]) : "r"(ad));
            }
            unsigned bfr[8][2];
            #pragma unroll
            for (int np = 0; np < 4; np++) {
                int quad = lane >> 3, rr = lane & 7;
                int row = kb + (quad & 1) * 8 + rr;
                int col = wn * 64 + np * 16 + (quad >> 1) * 8;
                unsigned bd = (unsigned)__cvta_generic_to_shared(Bs + row * PBNP + col);
                asm volatile("ldmatrix.sync.aligned.m8n8.x4.trans.shared.b16 {%0,%1,%2,%3}, [%4];"
                             : "=r"(bfr[np * 2][0]), "=r"(bfr[np * 2][1]),
                               "=r"(bfr[np * 2 + 1][0]), "=r"(bfr[np * 2 + 1][1]) : "r"(bd));
            }
            #pragma unroll
            for (int mt = 0; mt < 2; mt++)
                #pragma unroll
                for (int nt = 0; nt < 8; nt++)
                    MMA16816(acc[mt][nt], afr[mt], bfr[nt][0], bfr[nt][1]);
        }
        buf++; if (buf >= 3) buf = 0;
    }

    const int lr = lane >> 2, lc = (lane & 3) * 2;

    #pragma unroll
    for (int mt = 0; mt < 2; mt++) {
        #pragma unroll
        for (int half = 0; half < 2; half++) {
            int mrow = m0 + wm * 32 + mt * 16 + lr + half * 8;
            int bb = mrow >> 10, p = mrow & 1023;
            float s1 = 0.f, s2 = 0.f;
            #pragma unroll
            for (int nt = 0; nt < 8; nt++) {
                #pragma unroll
                for (int e = 0; e < 2; e++) {
                    int c = wn * 64 + nt * 8 + lc + e;
                    float t = acc[mt][nt][half * 2 + e] + bias[c] +
                              res[((size_t)(bb * C_ + c)) * NPOS + p];
                    acc[mt][nt][half * 2 + e] = t;
                    s1 += t; s2 += t * t;
                }
            }
            s1 += __shfl_xor_sync(0xffffffffu, s1, 1);
            s2 += __shfl_xor_sync(0xffffffffu, s2, 1);
            s1 += __shfl_xor_sync(0xffffffffu, s1, 2);
            s2 += __shfl_xor_sync(0xffffffffu, s2, 2);
            if ((lane & 3) == 0) {
                int r = wm * 32 + mt * 16 + lr + half * 8;
                sum4[wn][r] = s1;
                sq4[wn][r] = s2;
            }
        }
    }
    __syncthreads();
    if (tid < 64) {
        float t1 = sum4[0][tid] + sum4[1][tid] + sum4[2][tid] + sum4[3][tid];
        float t2 = sq4[0][tid] + sq4[1][tid] + sq4[2][tid] + sq4[3][tid];
        float mu  = t1 * (1.f / C_);
        float var = t2 * (1.f / C_) - mu * mu;
        smu[tid] = mu;
        srs[tid] = rsqrtf(var + 1e-5f);
    }
    __syncthreads();

    #pragma unroll
    for (int mt = 0; mt < 2; mt++) {
        #pragma unroll
        for (int half = 0; half < 2; half++) {
            int r = wm * 32 + mt * 16 + lr + half * 8;
            int mrow = m0 + r;
            float mu = smu[r], rs = srs[r];
            #pragma unroll
            for (int nt = 0; nt < 8; nt++) {
                int c = wn * 64 + nt * 8 + lc;
                float t0 = acc[mt][nt][half * 2 + 0];
                float t1v = acc[mt][nt][half * 2 + 1];
                *(float2*)&x3[(size_t)mrow * C_ + c] = make_float2(t0, t1v);
                float g0 = (t0 - mu) * rs * n2w[c] + n2b[c];
                float g1 = (t1v - mu) * rs * n2w[c + 1] + n2b[c + 1];
                __nv_bfloat162 pr = __floats2bfloat162_rn(g0, g1);
                *(__nv_bfloat162*)&x4b[(size_t)mrow * C_ + c] = pr;
            }
        }
    }
}

// ---------------------------------------------------------------------------
// Tensor-core flash attention — Q-tile 128 / CTA, 128 thr / 4 warps,
// warp = 32 q-rows (2 m-tiles), K/V fragments shared across m-tiles.
// Bias read from quarter-ordered bias9: 4x LDG.128 per mt, each a fully
// contiguous 512B warp chunk (4 L1 wavefronts).
// ---------------------------------------------------------------------------
__global__ __launch_bounds__(128, 3)
void attn_mma(const __nv_bfloat16* __restrict__ qkv,
              const __nv_bfloat16* __restrict__ bias9,
              __nv_bfloat16* __restrict__ out)
{
    __shared__ __align__(16) __nv_bfloat16 Qs[128][40];
    __shared__ __align__(16) __nv_bfloat16 Ks[3][64][40];
    __shared__ __align__(16) __nv_bfloat16 Vs[3][64][40];

    const int tid = threadIdx.x, lane = tid & 31, w = tid >> 5;
    const int qt = blockIdx.x, h = blockIdx.y, b = blockIdx.z;
    const int i0 = qt * 128;
    const size_t headBase = ((size_t)(b * HEADS + h)) * NPOS * DHEAD;
    const __nv_bfloat16* qg = qkv + headBase;
    const __nv_bfloat16* kg = qkv + 4194304u + headBase;
    const __nv_bfloat16* vg = qkv + 8388608u + headBase;

    // Q tile (128 rows) -> smem
    {
        int id = tid;
        #pragma unroll
        for (int it = 0; it < 4; it++, id += 128) {
            int r = id >> 2, kc = id & 3;
            const __nv_bfloat16* g = qg + (size_t)(i0 + r) * DHEAD + kc * 8;
            unsigned dst = (unsigned)__cvta_generic_to_shared(&Qs[r][kc * 8]);
            asm volatile("cp.async.cg.shared.global [%0], [%1], 16;\n" :: "r"(dst), "l"(g));
        }
        asm volatile("cp.async.commit_group;\n" ::: "memory");
    }

    auto loadKV = [&](int t, int buf) {
        int j0 = t * 64;
        #pragma unroll
        for (int it = 0; it < 2; it++) {
            int id = tid + it * 128;
            int r = id >> 2, kc = id & 3;
            const __nv_bfloat16* gk = kg + (size_t)(j0 + r) * DHEAD + kc * 8;
            unsigned dk = (unsigned)__cvta_generic_to_shared(&Ks[buf][r][kc * 8]);
            asm volatile("cp.async.cg.shared.global [%0], [%1], 16;\n" :: "r"(dk), "l"(gk));
            const __nv_bfloat16* gv = vg + (size_t)(j0 + r) * DHEAD + kc * 8;
            unsigned dv = (unsigned)__cvta_generic_to_shared(&Vs[buf][r][kc * 8]);
            asm volatile("cp.async.cg.shared.global [%0], [%1], 16;\n" :: "r"(dv), "l"(gv));
        }
        asm volatile("cp.async.commit_group;\n" ::: "memory");
    };

    loadKV(0, 0);

    unsigned qf[2][2][4];
    float oacc[2][4][4] = {};
    float lp[2][2] = {};
    const int lr = lane >> 2, lc = (lane & 3) * 2;
    const float k1 = 0.17677669529663687f * LOG2E;
    const __nv_bfloat162 k2 = __float2bfloat162_rn(k1);
    // Quarter-ordered bias base for this (head, lane)
    const __nv_bfloat16* bb0 = bias9 + ((size_t)h << 20) + lane * 8;

    int kbuf = 0;
    for (int t = 0; t < 16; t++) {
        if (t + 1 < 16) {
            int nb = kbuf + 1; if (nb == 3) nb = 0;
            loadKV(t + 1, nb);
            asm volatile("cp.async.wait_group 1;\n" ::: "memory");
        } else {
            asm volatile("cp.async.wait_group 0;\n" ::: "memory");
        }
        __syncthreads();

        if (t == 0) {
            #pragma unroll
            for (int mt = 0; mt < 2; mt++)
                #pragma unroll
                for (int kk = 0; kk < 2; kk++) {
                    unsigned ad = (unsigned)__cvta_generic_to_shared(
                        &Qs[w * 32 + mt * 16 + (lane & 15)][kk * 16 + (lane >> 4) * 8]);
                    asm volatile("ldmatrix.sync.aligned.m8n8.x4.shared.b16 {%0,%1,%2,%3}, [%4];"
                                 : "=r"(qf[mt][kk][0]), "=r"(qf[mt][kk][1]),
                                   "=r"(qf[mt][kk][2]), "=r"(qf[mt][kk][3]) : "r"(ad));
                }
        }

        // S phase: K fragments loaded once, feed both m-tiles
        float sacc[2][8][4] = {};
        #pragma unroll
        for (int kk = 0; kk < 2; kk++) {
            unsigned bfr[8][2];
            #pragma unroll
            for (int np = 0; np < 4; np++) {
                int g = lane >> 3;
                unsigned ad = (unsigned)__cvta_generic_to_shared(
                    &Ks[kbuf][(np * 2 + (g >> 1)) * 8 + (lane & 7)][kk * 16 + (g & 1) * 8]);
                asm volatile("ldmatrix.sync.aligned.m8n8.x4.shared.b16 {%0,%1,%2,%3}, [%4];"
                             : "=r"(bfr[np * 2][0]), "=r"(bfr[np * 2][1]),
                               "=r"(bfr[np * 2 + 1][0]), "=r"(bfr[np * 2 + 1][1]) : "r"(ad));
            }
            #pragma unroll
            for (int mt = 0; mt < 2; mt++)
                #pragma unroll
                for (int nt = 0; nt < 8; nt++)
                    MMA16816(sacc[mt][nt], qf[mt][kk], bfr[nt][0], bfr[nt][1]);
        }

        // Softmax: bias via quarter-ordered contiguous loads
        unsigned pfr[2][8][2];
        #pragma unroll
        for (int mt = 0; mt < 2; mt++) {
            const __nv_bfloat16* bl =
                bb0 + (size_t)(((qt * 8 + w * 2 + mt) * 16 + t)) * 1024u;
            uint4 v0 = *(const uint4*)(bl);
            uint4 v1 = *(const uint4*)(bl + 256);
            uint4 v2 = *(const uint4*)(bl + 512);
            uint4 v3 = *(const uint4*)(bl + 768);
            unsigned wv[2][8] = {
                {v0.x, v0.y, v0.z, v0.w, v1.x, v1.y, v1.z, v1.w},
                {v2.x, v2.y, v2.z, v2.w, v3.x, v3.y, v3.z, v3.w}};
            #pragma unroll
            for (int half = 0; half < 2; half++) {
                float rsum = 0.f;
                #pragma unroll
                for (int nt = 0; nt < 8; nt++) {
                    __nv_bfloat162 bbv = *reinterpret_cast<__nv_bfloat162*>(&wv[half][nt]);
                    __nv_bfloat162 s2 = __floats2bfloat162_rn(
                        sacc[mt][nt][half * 2 + 0], sacc[mt][nt][half * 2 + 1]);
                    __nv_bfloat162 arg = __hfma2(s2, k2, bbv);
                    unsigned argr = *reinterpret_cast<unsigned*>(&arg);
                    unsigned p2r;
                    asm("ex2.approx.ftz.bf16x2 %0, %1;" : "=r"(p2r) : "r"(argr));
                    pfr[mt][nt][half] = p2r;
                    float2 pf2 = __bfloat1622float2(
                        *reinterpret_cast<__nv_bfloat162*>(&p2r));
                    rsum += pf2.x + pf2.y;
                }
                lp[mt][half] += rsum;
            }
        }

        // PV phase: V fragments loaded once, feed both m-tiles
        #pragma unroll
        for (int kc = 0; kc < 4; kc++) {
            unsigned bv[4][2];
            #pragma unroll
            for (int np = 0; np < 2; np++) {
                int quad = lane >> 3, rr = lane & 7;
                unsigned ad = (unsigned)__cvta_generic_to_shared(
                    &Vs[kbuf][kc * 16 + (quad & 1) * 8 + rr][np * 16 + (quad >> 1) * 8]);
                asm volatile("ldmatrix.sync.aligned.m8n8.x4.trans.shared.b16 {%0,%1,%2,%3}, [%4];"
                             : "=r"(bv[np * 2][0]), "=r"(bv[np * 2][1]),
                               "=r"(bv[np * 2 + 1][0]), "=r"(bv[np * 2 + 1][1]) : "r"(ad));
            }
            #pragma unroll
            for (int mt = 0; mt < 2; mt++) {
                unsigned pf[4];
                pf[0] = pfr[mt][2 * kc][0];
                pf[1] = pfr[mt][2 * kc][1];
                pf[2] = pfr[mt][2 * kc + 1][0];
                pf[3] = pfr[mt][2 * kc + 1][1];
                #pragma unroll
                for (int nv = 0; nv < 4; nv++)
                    MMA16816(oacc[mt][nv], pf, bv[nv][0], bv[nv][1]);
            }
        }

        kbuf++; if (kbuf == 3) kbuf = 0;
    }

    // Finalize
    #pragma unroll
    for (int mt = 0; mt < 2; mt++) {
        float inv[2];
        #pragma unroll
        for (int half = 0; half < 2; half++) {
            float l = lp[mt][half];
            l += __shfl_xor_sync(0xffffffffu, l, 1);
            l += __shfl_xor_sync(0xffffffffu, l, 2);
            inv[half] = 1.f / l;
        }
        #pragma unroll
        for (int half = 0; half < 2; half++) {
            int i = i0 + w * 32 + mt * 16 + lr + half * 8;
            __nv_bfloat16* orow = out + ((size_t)(b * NPOS + i)) * C_ + h * DHEAD;
            #pragma unroll
            for (int nv = 0; nv < 4; nv++) {
                __nv_bfloat162 pr = __floats2bfloat162_rn(
                    oacc[mt][nv][half * 2 + 0] * inv[half],
                    oacc[mt][nv][half * 2 + 1] * inv[half]);
                *(__nv_bfloat162*)&orow[nv * 8 + lc] = pr;
            }
        }
    }
}

// ---------------------------------------------------------------------------
// Host launch
// ---------------------------------------------------------------------------
extern "C" void kernel_launch(void* const* d_in, const int* in_sizes, int n_in,
                              void* d_out, int out_size)
{
    const float* x       = (const float*)d_in[0];
    const float* qkv_w   = (const float*)d_in[1];
    const float* proj_w  = (const float*)d_in[2];
    const float* proj_b  = (const float*)d_in[3];
    const float* ffn_w1  = (const float*)d_in[4];
    const float* ffn_b1  = (const float*)d_in[5];
    const float* ffn_w2  = (const float*)d_in[6];
    const float* ffn_b2  = (const float*)d_in[7];
    const float* n1w     = (const float*)d_in[8];
    const float* n1b     = (const float*)d_in[9];
    const float* n2w     = (const float*)d_in[10];
    const float* n2b     = (const float*)d_in[11];
    const float* btab    = (const float*)d_in[12];
    const int*   ridx    = (const int*)d_in[13];
    float* out = (float*)d_out;

    float* scratch = nullptr;
    cudaGetSymbolAddress((void**)&scratch, g_scratch);

    __nv_bfloat16* wb    = (__nv_bfloat16*)(scratch + OFF_WB);
    __nv_bfloat16* x1b   = (__nv_bfloat16*)(scratch + OFF_X1B);
    __nv_bfloat16* qkvb  = (__nv_bfloat16*)(scratch + OFF_QKVB);
    __nv_bfloat16* bias9 = (__nv_bfloat16*)(scratch + OFF_BIAS8);
    __nv_bfloat16* attnb = (__nv_bfloat16*)(scratch + OFF_ATTNB);
    float*         x3    = scratch + OFF_X3;
    __nv_bfloat16* x4b   = (__nv_bfloat16*)(scratch + OFF_X4B);
    __nv_bfloat16* h1b   = (__nv_bfloat16*)(scratch + OFF_H1B);

    static bool attrSet = false;
    if (!attrSet) {
        cudaFuncSetAttribute(proj_ln_kernel,
                             cudaFuncAttributeMaxDynamicSharedMemorySize, PSMEM_BYTES);
        attrSet = true;
    }

    // 0. Merged prep: weight conversion + quarter-ordered bias precompute
    prep_kernel<<<4096, 256>>>(qkv_w, proj_w, ffn_w1, ffn_w2, wb, btab, ridx, bias9);

    // 1. LN1 (fused transpose)
    ln1_kernel<<<dim3(NPOS / 32, B_), 256>>>(x, n1w, n1b, x1b);

    // 2. QKV GEMM -> bf16 q/k/v head layout
    mma_gemm<0><<<dim3(768 / 128, NTOK / 128), 128>>>(
        x1b, wb + WB_QKV, NTOK, 768, C_, nullptr, nullptr, nullptr, qkvb);

    // 3. Flash attention (Q-tile 128, shared K/V fragments, quarter bias)
    attn_mma<<<dim3(NPOS / 128, HEADS, B_), 128>>>(qkvb, bias9, attnb);

    // 4. Fused proj GEMM + bias + residual(x) + LN2 -> x3 / x4b (64-row CTAs)
    proj_ln_kernel<<<NTOK / 64, 256, PSMEM_BYTES>>>(
        attnb, wb + WB_PROJ, proj_b, x, n2w, n2b, x3, x4b);

    // 5. FFN1 + GELU -> bf16 h1
    mma_gemm<2><<<dim3(HID / 128, NTOK / 128), 128>>>(
        x4b, wb + WB_W1, NTOK, HID, C_, ffn_b1, nullptr, nullptr, h1b);

    // 6. FFN2 + bias + residual(x3) -> fp32 output (B,C,H,W)
    mma_gemm<3><<<dim3(C_ / 128, NTOK / 128), 128>>>(
        h1b, wb + WB_W2, NTOK, C_, HID, ffn_b2, x3, out, nullptr);
}

// round 17
// speedup vs baseline: 1.2450x; 1.0216x over previous
#include <cuda_runtime.h>
#include <cuda_bf16.h>
#include <math.h>
#include <stdint.h>

// Problem constants
#define B_    16
#define C_    256
#define NTOK  16384
#define NPOS  1024
#define HEADS 8
#define DHEAD 32
#define HID   1024
#define LOG2E 1.4426950408889634f

// ---------------------------------------------------------------------------
// Scratch layout (float units)
// ---------------------------------------------------------------------------
#define OFF_WB     0u
#define WB_QKV     0u
#define WB_PROJ    196608u
#define WB_W1      262144u
#define WB_W2      524288u
#define WB_TOTAL   786432u

#define OFF_X1B    524288u
#define OFF_QKVB   2621440u
#define OFF_BIAS8  8912896u
#define OFF_ATTNB  13107200u
#define OFF_X3     15204352u
#define OFF_X4B    19398656u
#define OFF_H1B    21495808u
#define SCRATCH_FLOATS 33554432u

__device__ float g_scratch[SCRATCH_FLOATS];

// ---------------------------------------------------------------------------
// Merged prep + LN1.
// Blocks [0, 3072): weight fp32 -> bf16.
// Blocks [3072, 4096): bias precompute, quarter-ordered fragment layout.
// Blocks [4096, 4608): LN1 fused transpose (one block = 32 positions).
// ---------------------------------------------------------------------------
__global__ __launch_bounds__(256)
void prep_kernel(const float* __restrict__ a, const float* __restrict__ b,
                 const float* __restrict__ c, const float* __restrict__ d,
                 __nv_bfloat16* __restrict__ wout,
                 const float* __restrict__ table, const int* __restrict__ ridx,
                 __nv_bfloat16* __restrict__ bias9,
                 const float* __restrict__ x, const float* __restrict__ n1w,
                 const float* __restrict__ n1b, __nv_bfloat16* __restrict__ x1b)
{
    if (blockIdx.x < 3072) {
        unsigned i = blockIdx.x * 256u + threadIdx.x;
        if (i < WB_PROJ)            wout[i] = __float2bfloat16(a[i]);
        else if (i < WB_W1)         wout[i] = __float2bfloat16(b[i - WB_PROJ]);
        else if (i < WB_W2)         wout[i] = __float2bfloat16(c[i - WB_W1]);
        else if (i < WB_TOTAL)      wout[i] = __float2bfloat16(d[i - WB_W2]);
        return;
    }

    if (blockIdx.x < 4096) {
        __shared__ __nv_bfloat16 vals[16][64][HEADS];   // 16 KB
        const int blk = blockIdx.x - 3072;      // 0..1023
        const int ib = blk >> 4;
        const int jb = blk & 15;
        const int tid = threadIdx.x;

        #pragma unroll
        for (int it = 0; it < 4; it++) {
            int pos = it * 256 + tid;
            int r = pos >> 6, cc = pos & 63;
            int idx = ridx[(size_t)(ib * 16 + r) * NPOS + jb * 64 + cc];
            const float* tr = table + (size_t)idx * HEADS;
            #pragma unroll
            for (int h = 0; h < HEADS; h++)
                vals[r][cc][h] = __float2bfloat16(tr[h] * LOG2E);
        }
        __syncthreads();

        #pragma unroll
        for (int h = 0; h < HEADS; h++) {
            #pragma unroll
            for (int it = 0; it < 4; it++) {
                int dd = it * 256 + tid;
                int q = dd >> 8, rem = dd & 255;
                int lane = rem >> 3, j = rem & 7;
                int k = q * 8 + j;
                int half = k >> 4, nt = (k >> 1) & 7, e = k & 1;
                int r = half * 8 + (lane >> 2);
                int cc = nt * 8 + (lane & 3) * 2 + e;
                bias9[(size_t)h * 1048576u + (size_t)blk * 1024u + dd] = vals[r][cc][h];
            }
        }
        return;
    }

    // LN1: block = 32 positions of one image
    {
        __shared__ float tile[C_][33];
        __shared__ float red1[8][32], red2[8][32];
        __shared__ float smu[32], srs[32];

        const int blk = blockIdx.x - 4096;       // 0..511
        const int bb = blk >> 5, p0 = (blk & 31) * 32;
        const int tid = threadIdx.x;

        #pragma unroll
        for (int it = 0; it < 32; it++) {
            int id = it * 256 + tid;
            int cidx = id >> 5, pp = id & 31;
            tile[cidx][pp] = x[((size_t)(bb * C_ + cidx)) * NPOS + p0 + pp];
        }
        __syncthreads();

        {
            int token = tid & 31, part = tid >> 5;
            float s1 = 0.f, s2 = 0.f;
            #pragma unroll
            for (int cc = 0; cc < 32; cc++) {
                float v = tile[part * 32 + cc][token];
                s1 += v; s2 += v * v;
            }
            red1[part][token] = s1;
            red2[part][token] = s2;
        }
        __syncthreads();
        if (tid < 32) {
            float t1 = 0.f, t2 = 0.f;
            #pragma unroll
            for (int p = 0; p < 8; p++) { t1 += red1[p][tid]; t2 += red2[p][tid]; }
            float mu  = t1 * (1.f / C_);
            float var = t2 * (1.f / C_) - mu * mu;
            smu[tid] = mu;
            srs[tid] = rsqrtf(var + 1e-5f);
        }
        __syncthreads();

        const float wc = n1w[tid], bc = n1b[tid];
        #pragma unroll
        for (int it = 0; it < 32; it++) {
            float v = tile[tid][it];
            x1b[((size_t)(bb * NPOS + p0 + it)) * C_ + tid] =
                __float2bfloat16((v - smu[it]) * srs[it] * wc + bc);
        }
    }
}

// ---------------------------------------------------------------------------
// bf16 mma.sync GEMM (128 thr / 4 warps, warp tile 64x64) — EPI 0/2/3
// ---------------------------------------------------------------------------
#define AKP 40
#define BNP 136

#define MMA16816(acc, af, b0, b1)                                              \
    asm volatile("mma.sync.aligned.m16n8k16.row.col.f32.bf16.bf16.f32 "        \
                 "{%0,%1,%2,%3}, {%4,%5,%6,%7}, {%8,%9}, {%0,%1,%2,%3};"       \
                 : "+f"(acc[0]), "+f"(acc[1]), "+f"(acc[2]), "+f"(acc[3])      \
                 : "r"(af[0]), "r"(af[1]), "r"(af[2]), "r"(af[3]),             \
                   "r"(b0), "r"(b1))

template<int EPI>
__global__ __launch_bounds__(128)
void mma_gemm(const __nv_bfloat16* __restrict__ A, const __nv_bfloat16* __restrict__ Bw,
              int M, int N, int K,
              const float* __restrict__ bias, const float* __restrict__ res,
              float* __restrict__ outf, __nv_bfloat16* __restrict__ outb)
{
    __shared__ __align__(16) __nv_bfloat16 As[3][128][AKP];
    __shared__ __align__(16) __nv_bfloat16 Bs[3][32][BNP];

    const int tid = threadIdx.x, lane = tid & 31, wid = tid >> 5;
    const int wm = wid >> 1, wn = wid & 1;
    const int m0 = blockIdx.y * 128, n0 = blockIdx.x * 128;

    float acc[4][8][4] = {};
    const int S = K >> 5;

    auto loadStage = [&](int s, int buf) {
        int kpos = s << 5;
        #pragma unroll
        for (int j = 0; j < 4; j++) {
            int id = tid + j * 128;
            int r = id >> 2, kc = id & 3;
            const __nv_bfloat16* g = A + (size_t)(m0 + r) * K + kpos + kc * 8;
            unsigned dst = (unsigned)__cvta_generic_to_shared(&As[buf][r][kc * 8]);
            asm volatile("cp.async.cg.shared.global [%0], [%1], 16;\n"
                         :: "r"(dst), "l"(g));
        }
        #pragma unroll
        for (int j = 0; j < 4; j++) {
            int id = tid + j * 128;
            int r = id >> 4, nc = id & 15;
            const __nv_bfloat16* g = Bw + (size_t)(kpos + r) * N + n0 + nc * 8;
            unsigned dst = (unsigned)__cvta_generic_to_shared(&Bs[buf][r][nc * 8]);
            asm volatile("cp.async.cg.shared.global [%0], [%1], 16;\n"
                         :: "r"(dst), "l"(g));
        }
        asm volatile("cp.async.commit_group;\n" ::: "memory");
    };

    loadStage(0, 0);
    loadStage(1, 1);

    int buf = 0;
    for (int s = 0; s < S; s++) {
        asm volatile("cp.async.wait_group 1;\n" ::: "memory");
        __syncthreads();
        if (s + 2 < S) {
            int nb = buf + 2; if (nb >= 3) nb -= 3;
            loadStage(s + 2, nb);
        }

        #pragma unroll
        for (int ks = 0; ks < 2; ks++) {
            const int kb = ks * 16;
            unsigned afr[4][4];
            #pragma unroll
            for (int mt = 0; mt < 4; mt++) {
                unsigned ad = (unsigned)__cvta_generic_to_shared(
                    &As[buf][wm * 64 + mt * 16 + (lane & 15)][kb + (lane >> 4) * 8]);
                asm volatile("ldmatrix.sync.aligned.m8n8.x4.shared.b16 {%0,%1,%2,%3}, [%4];"
                             : "=r"(afr[mt][0]), "=r"(afr[mt][1]),
                               "=r"(afr[mt][2]), "=r"(afr[mt][3]) : "r"(ad));
            }
            unsigned bfr[8][2];
            #pragma unroll
            for (int np = 0; np < 4; np++) {
                int quad = lane >> 3, rr = lane & 7;
                int row = kb + (quad & 1) * 8 + rr;
                int col = wn * 64 + np * 16 + (quad >> 1) * 8;
                unsigned bd = (unsigned)__cvta_generic_to_shared(&Bs[buf][row][col]);
                asm volatile("ldmatrix.sync.aligned.m8n8.x4.trans.shared.b16 {%0,%1,%2,%3}, [%4];"
                             : "=r"(bfr[np * 2][0]), "=r"(bfr[np * 2][1]),
                               "=r"(bfr[np * 2 + 1][0]), "=r"(bfr[np * 2 + 1][1]) : "r"(bd));
            }
            #pragma unroll
            for (int mt = 0; mt < 4; mt++)
                #pragma unroll
                for (int nt = 0; nt < 8; nt++)
                    MMA16816(acc[mt][nt], afr[mt], bfr[nt][0], bfr[nt][1]);
        }
        buf++; if (buf >= 3) buf = 0;
    }

    const int lr = lane >> 2, lc = (lane & 3) * 2;
    #pragma unroll
    for (int mt = 0; mt < 4; mt++) {
        #pragma unroll
        for (int half = 0; half < 2; half++) {
            int mrow = m0 + wm * 64 + mt * 16 + lr + half * 8;
            int bb = mrow >> 10, p = mrow & 1023;
            #pragma unroll
            for (int nt = 0; nt < 8; nt++) {
                if (EPI == 0) {
                    int c = n0 + wn * 64 + nt * 8 + lc;
                    int part = c >> 8, hh = (c >> 5) & 7, d = c & 31;
                    __nv_bfloat162 pr = __floats2bfloat162_rn(
                        acc[mt][nt][half * 2 + 0], acc[mt][nt][half * 2 + 1]);
                    *(__nv_bfloat162*)&outb[(size_t)part * 4194304u +
                        (((size_t)(bb * HEADS + hh)) * NPOS + p) * DHEAD + d] = pr;
                } else {
                    #pragma unroll
                    for (int e = 0; e < 2; e++) {
                        int c = n0 + wn * 64 + nt * 8 + lc + e;
                        float v = acc[mt][nt][half * 2 + e];
                        if (EPI == 2) {
                            float t = v + bias[c];
                            outb[(size_t)mrow * N + c] = __float2bfloat16(
                                0.5f * t * (1.f + erff(t * 0.70710678118654752f)));
                        } else {
                            outf[((size_t)(bb * C_ + c)) * NPOS + p] =
                                v + bias[c] + res[(size_t)mrow * C_ + c];
                        }
                    }
                }
            }
        }
    }
}

// ---------------------------------------------------------------------------
// Fused proj GEMM + bias + residual + LayerNorm2 (64-row CTAs)
// ---------------------------------------------------------------------------
#define PBNP 264
#define PA_STG (64 * AKP)
#define PB_STG (32 * PBNP)
#define PSMEM_BYTES ((3 * PA_STG + 3 * PB_STG) * 2)

__global__ __launch_bounds__(256)
void proj_ln_kernel(const __nv_bfloat16* __restrict__ A, const __nv_bfloat16* __restrict__ Bw,
                    const float* __restrict__ bias, const float* __restrict__ res,
                    const float* __restrict__ n2w, const float* __restrict__ n2b,
                    float* __restrict__ x3, __nv_bfloat16* __restrict__ x4b)
{
    extern __shared__ __align__(16) __nv_bfloat16 dsm[];
    __nv_bfloat16* AsBase = dsm;
    __nv_bfloat16* BsBase = dsm + 3 * PA_STG;
    __shared__ float sum4[4][64], sq4[4][64];
    __shared__ float smu[64], srs[64];

    const int tid = threadIdx.x, lane = tid & 31, wid = tid >> 5;
    const int wm = wid >> 2, wn = wid & 3;
    const int m0 = blockIdx.x * 64;
    const int K = C_, N = C_;

    float acc[2][8][4] = {};

    auto loadStage = [&](int s, int buf) {
        int kpos = s << 5;
        __nv_bfloat16* As = AsBase + buf * PA_STG;
        __nv_bfloat16* Bs = BsBase + buf * PB_STG;
        {
            int r = tid >> 2, kc = tid & 3;
            const __nv_bfloat16* g = A + (size_t)(m0 + r) * K + kpos + kc * 8;
            unsigned dst = (unsigned)__cvta_generic_to_shared(As + r * AKP + kc * 8);
            asm volatile("cp.async.cg.shared.global [%0], [%1], 16;\n" :: "r"(dst), "l"(g));
        }
        #pragma unroll
        for (int j = 0; j < 4; j++) {
            int id = tid + j * 256;
            int r = id >> 5, nc = id & 31;
            const __nv_bfloat16* g = Bw + (size_t)(kpos + r) * N + nc * 8;
            unsigned dst = (unsigned)__cvta_generic_to_shared(Bs + r * PBNP + nc * 8);
            asm volatile("cp.async.cg.shared.global [%0], [%1], 16;\n" :: "r"(dst), "l"(g));
        }
        asm volatile("cp.async.commit_group;\n" ::: "memory");
    };

    loadStage(0, 0);
    loadStage(1, 1);

    int buf = 0;
    const int S = K >> 5;
    for (int s = 0; s < S; s++) {
        asm volatile("cp.async.wait_group 1;\n" ::: "memory");
        __syncthreads();
        if (s + 2 < S) {
            int nb = buf + 2; if (nb >= 3) nb -= 3;
            loadStage(s + 2, nb);
        }
        __nv_bfloat16* As = AsBase + buf * PA_STG;
        __nv_bfloat16* Bs = BsBase + buf * PB_STG;

        #pragma unroll
        for (int ks = 0; ks < 2; ks++) {
            const int kb = ks * 16;
            unsigned afr[2][4];
            #pragma unroll
            for (int mt = 0; mt < 2; mt++) {
                unsigned ad = (unsigned)__cvta_generic_to_shared(
                    As + (wm * 32 + mt * 16 + (lane & 15)) * AKP + kb + (lane >> 4) * 8);
                asm volatile("ldmatrix.sync.aligned.m8n8.x4.shared.b16 {%0,%1,%2,%3}, [%4];"
                             : "=r"(afr[mt][0]), "=r"(afr[mt][1]),
                               "=r"(afr[mt][2]), "=r"(afr[mt][3]) : "r"(ad));
            }
            unsigned bfr[8][2];
            #pragma unroll
            for (int np = 0; np < 4; np++) {
                int quad = lane >> 3, rr = lane & 7;
                int row = kb + (quad & 1) * 8 + rr;
                int col = wn * 64 + np * 16 + (quad >> 1) * 8;
                unsigned bd = (unsigned)__cvta_generic_to_shared(Bs + row * PBNP + col);
                asm volatile("ldmatrix.sync.aligned.m8n8.x4.trans.shared.b16 {%0,%1,%2,%3}, [%4];"
                             : "=r"(bfr[np * 2][0]), "=r"(bfr[np * 2][1]),
                               "=r"(bfr[np * 2 + 1][0]), "=r"(bfr[np * 2 + 1][1]) : "r"(bd));
            }
            #pragma unroll
            for (int mt = 0; mt < 2; mt++)
                #pragma unroll
                for (int nt = 0; nt < 8; nt++)
                    MMA16816(acc[mt][nt], afr[mt], bfr[nt][0], bfr[nt][1]);
        }
        buf++; if (buf >= 3) buf = 0;
    }

    const int lr = lane >> 2, lc = (lane & 3) * 2;

    #pragma unroll
    for (int mt = 0; mt < 2; mt++) {
        #pragma unroll
        for (int half = 0; half < 2; half++) {
            int mrow = m0 + wm * 32 + mt * 16 + lr + half * 8;
            int bb = mrow >> 10, p = mrow & 1023;
            float s1 = 0.f, s2 = 0.f;
            #pragma unroll
            for (int nt = 0; nt < 8; nt++) {
                #pragma unroll
                for (int e = 0; e < 2; e++) {
                    int c = wn * 64 + nt * 8 + lc + e;
                    float t = acc[mt][nt][half * 2 + e] + bias[c] +
                              res[((size_t)(bb * C_ + c)) * NPOS + p];
                    acc[mt][nt][half * 2 + e] = t;
                    s1 += t; s2 += t * t;
                }
            }
            s1 += __shfl_xor_sync(0xffffffffu, s1, 1);
            s2 += __shfl_xor_sync(0xffffffffu, s2, 1);
            s1 += __shfl_xor_sync(0xffffffffu, s1, 2);
            s2 += __shfl_xor_sync(0xffffffffu, s2, 2);
            if ((lane & 3) == 0) {
                int r = wm * 32 + mt * 16 + lr + half * 8;
                sum4[wn][r] = s1;
                sq4[wn][r] = s2;
            }
        }
    }
    __syncthreads();
    if (tid < 64) {
        float t1 = sum4[0][tid] + sum4[1][tid] + sum4[2][tid] + sum4[3][tid];
        float t2 = sq4[0][tid] + sq4[1][tid] + sq4[2][tid] + sq4[3][tid];
        float mu  = t1 * (1.f / C_);
        float var = t2 * (1.f / C_) - mu * mu;
        smu[tid] = mu;
        srs[tid] = rsqrtf(var + 1e-5f);
    }
    __syncthreads();

    #pragma unroll
    for (int mt = 0; mt < 2; mt++) {
        #pragma unroll
        for (int half = 0; half < 2; half++) {
            int r = wm * 32 + mt * 16 + lr + half * 8;
            int mrow = m0 + r;
            float mu = smu[r], rs = srs[r];
            #pragma unroll
            for (int nt = 0; nt < 8; nt++) {
                int c = wn * 64 + nt * 8 + lc;
                float t0 = acc[mt][nt][half * 2 + 0];
                float t1v = acc[mt][nt][half * 2 + 1];
                *(float2*)&x3[(size_t)mrow * C_ + c] = make_float2(t0, t1v);
                float g0 = (t0 - mu) * rs * n2w[c] + n2b[c];
                float g1 = (t1v - mu) * rs * n2w[c + 1] + n2b[c + 1];
                __nv_bfloat162 pr = __floats2bfloat162_rn(g0, g1);
                *(__nv_bfloat162*)&x4b[(size_t)mrow * C_ + c] = pr;
            }
        }
    }
}

// ---------------------------------------------------------------------------
// Tensor-core flash attention — Q-tile 128 / CTA, 128 thr / 4 warps,
// warp = 32 q-rows (2 m-tiles), K/V fragments shared across m-tiles,
// quarter-ordered bias (contiguous 512B warp loads), running pointers.
// ---------------------------------------------------------------------------
__global__ __launch_bounds__(128, 3)
void attn_mma(const __nv_bfloat16* __restrict__ qkv,
              const __nv_bfloat16* __restrict__ bias9,
              __nv_bfloat16* __restrict__ out)
{
    __shared__ __align__(16) __nv_bfloat16 Qs[128][40];
    __shared__ __align__(16) __nv_bfloat16 Ks[3][64][40];
    __shared__ __align__(16) __nv_bfloat16 Vs[3][64][40];

    const int tid = threadIdx.x, lane = tid & 31, w = tid >> 5;
    const int qt = blockIdx.x, h = blockIdx.y, b = blockIdx.z;
    const int i0 = qt * 128;
    const size_t headBase = ((size_t)(b * HEADS + h)) * NPOS * DHEAD;
    const __nv_bfloat16* qg = qkv + headBase;

    // Running global K/V pointers (advance 2048 halves per tile)
    const int lr0 = tid >> 2, lkc = tid & 3;
    const __nv_bfloat16* gk = qkv + 4194304u + headBase + (size_t)lr0 * DHEAD + lkc * 8;
    const __nv_bfloat16* gv = qkv + 8388608u + headBase + (size_t)lr0 * DHEAD + lkc * 8;

    // Q tile (128 rows) -> smem
    {
        int id = tid;
        #pragma unroll
        for (int it = 0; it < 4; it++, id += 128) {
            int r = id >> 2, kc = id & 3;
            const __nv_bfloat16* g = qg + (size_t)(i0 + r) * DHEAD + kc * 8;
            unsigned dst = (unsigned)__cvta_generic_to_shared(&Qs[r][kc * 8]);
            asm volatile("cp.async.cg.shared.global [%0], [%1], 16;\n" :: "r"(dst), "l"(g));
        }
        asm volatile("cp.async.commit_group;\n" ::: "memory");
    }

    auto loadKV = [&](const __nv_bfloat16* gkp, const __nv_bfloat16* gvp, int buf) {
        #pragma unroll
        for (int it = 0; it < 2; it++) {
            int r = lr0 + it * 32;
            unsigned dk = (unsigned)__cvta_generic_to_shared(&Ks[buf][r][lkc * 8]);
            asm volatile("cp.async.cg.shared.global [%0], [%1], 16;\n"
                         :: "r"(dk), "l"(gkp + (size_t)it * 32 * DHEAD));
            unsigned dv = (unsigned)__cvta_generic_to_shared(&Vs[buf][r][lkc * 8]);
            asm volatile("cp.async.cg.shared.global [%0], [%1], 16;\n"
                         :: "r"(dv), "l"(gvp + (size_t)it * 32 * DHEAD));
        }
        asm volatile("cp.async.commit_group;\n" ::: "memory");
    };

    loadKV(gk, gv, 0);

    unsigned qf[2][2][4];
    float oacc[2][4][4] = {};
    float lp[2][2] = {};
    const int lr = lane >> 2, lc = (lane & 3) * 2;
    const float k1 = 0.17677669529663687f * LOG2E;
    const __nv_bfloat162 k2 = __float2bfloat162_rn(k1);
    // Running quarter-ordered bias pointers per m-tile (advance 1024/tile)
    const __nv_bfloat16* bl0 = bias9 + ((size_t)h << 20) + lane * 8 +
        (size_t)((qt * 8 + w * 2 + 0) * 16) * 1024u;
    const __nv_bfloat16* bl1 = bl0 + 16384u;   // mt=1: +16*1024

    int kbuf = 0;
    for (int t = 0; t < 16; t++) {
        if (t + 1 < 16) {
            int nb = kbuf + 1; if (nb == 3) nb = 0;
            loadKV(gk + (size_t)(t + 1) * 2048u, gv + (size_t)(t + 1) * 2048u, nb);
            asm volatile("cp.async.wait_group 1;\n" ::: "memory");
        } else {
            asm volatile("cp.async.wait_group 0;\n" ::: "memory");
        }
        __syncthreads();

        if (t == 0) {
            #pragma unroll
            for (int mt = 0; mt < 2; mt++)
                #pragma unroll
                for (int kk = 0; kk < 2; kk++) {
                    unsigned ad = (unsigned)__cvta_generic_to_shared(
                        &Qs[w * 32 + mt * 16 + (lane & 15)][kk * 16 + (lane >> 4) * 8]);
                    asm volatile("ldmatrix.sync.aligned.m8n8.x4.shared.b16 {%0,%1,%2,%3}, [%4];"
                                 : "=r"(qf[mt][kk][0]), "=r"(qf[mt][kk][1]),
                                   "=r"(qf[mt][kk][2]), "=r"(qf[mt][kk][3]) : "r"(ad));
                }
        }

        // S phase: K fragments loaded once, feed both m-tiles
        float sacc[2][8][4] = {};
        #pragma unroll
        for (int kk = 0; kk < 2; kk++) {
            unsigned bfr[8][2];
            #pragma unroll
            for (int np = 0; np < 4; np++) {
                int g = lane >> 3;
                unsigned ad = (unsigned)__cvta_generic_to_shared(
                    &Ks[kbuf][(np * 2 + (g >> 1)) * 8 + (lane & 7)][kk * 16 + (g & 1) * 8]);
                asm volatile("ldmatrix.sync.aligned.m8n8.x4.shared.b16 {%0,%1,%2,%3}, [%4];"
                             : "=r"(bfr[np * 2][0]), "=r"(bfr[np * 2][1]),
                               "=r"(bfr[np * 2 + 1][0]), "=r"(bfr[np * 2 + 1][1]) : "r"(ad));
            }
            #pragma unroll
            for (int mt = 0; mt < 2; mt++)
                #pragma unroll
                for (int nt = 0; nt < 8; nt++)
                    MMA16816(sacc[mt][nt], qf[mt][kk], bfr[nt][0], bfr[nt][1]);
        }

        // Softmax: bias via quarter-ordered contiguous loads (running ptrs)
        unsigned pfr[2][8][2];
        #pragma unroll
        for (int mt = 0; mt < 2; mt++) {
            const __nv_bfloat16* bl = (mt == 0 ? bl0 : bl1) + (size_t)t * 1024u;
            uint4 v0 = *(const uint4*)(bl);
            uint4 v1 = *(const uint4*)(bl + 256);
            uint4 v2 = *(const uint4*)(bl + 512);
            uint4 v3 = *(const uint4*)(bl + 768);
            unsigned wv[2][8] = {
                {v0.x, v0.y, v0.z, v0.w, v1.x, v1.y, v1.z, v1.w},
                {v2.x, v2.y, v2.z, v2.w, v3.x, v3.y, v3.z, v3.w}};
            #pragma unroll
            for (int half = 0; half < 2; half++) {
                float rsum = 0.f;
                #pragma unroll
                for (int nt = 0; nt < 8; nt++) {
                    __nv_bfloat162 bbv = *reinterpret_cast<__nv_bfloat162*>(&wv[half][nt]);
                    __nv_bfloat162 s2 = __floats2bfloat162_rn(
                        sacc[mt][nt][half * 2 + 0], sacc[mt][nt][half * 2 + 1]);
                    __nv_bfloat162 arg = __hfma2(s2, k2, bbv);
                    unsigned argr = *reinterpret_cast<unsigned*>(&arg);
                    unsigned p2r;
                    asm("ex2.approx.ftz.bf16x2 %0, %1;" : "=r"(p2r) : "r"(argr));
                    pfr[mt][nt][half] = p2r;
                    float2 pf2 = __bfloat1622float2(
                        *reinterpret_cast<__nv_bfloat162*>(&p2r));
                    rsum += pf2.x + pf2.y;
                }
                lp[mt][half] += rsum;
            }
        }

        // PV phase: V fragments loaded once, feed both m-tiles
        #pragma unroll
        for (int kc = 0; kc < 4; kc++) {
            unsigned bv[4][2];
            #pragma unroll
            for (int np = 0; np < 2; np++) {
                int quad = lane >> 3, rr = lane & 7;
                unsigned ad = (unsigned)__cvta_generic_to_shared(
                    &Vs[kbuf][kc * 16 + (quad & 1) * 8 + rr][np * 16 + (quad >> 1) * 8]);
                asm volatile("ldmatrix.sync.aligned.m8n8.x4.trans.shared.b16 {%0,%1,%2,%3}, [%4];"
                             : "=r"(bv[np * 2][0]), "=r"(bv[np * 2][1]),
                               "=r"(bv[np * 2 + 1][0]), "=r"(bv[np * 2 + 1][1]) : "r"(ad));
            }
            #pragma unroll
            for (int mt = 0; mt < 2; mt++) {
                unsigned pf[4];
                pf[0] = pfr[mt][2 * kc][0];
                pf[1] = pfr[mt][2 * kc][1];
                pf[2] = pfr[mt][2 * kc + 1][0];
                pf[3] = pfr[mt][2 * kc + 1][1];
                #pragma unroll
                for (int nv = 0; nv < 4; nv++)
                    MMA16816(oacc[mt][nv], pf, bv[nv][0], bv[nv][1]);
            }
        }

        kbuf++; if (kbuf == 3) kbuf = 0;
    }

    // Finalize
    #pragma unroll
    for (int mt = 0; mt < 2; mt++) {
        float inv[2];
        #pragma unroll
        for (int half = 0; half < 2; half++) {
            float l = lp[mt][half];
            l += __shfl_xor_sync(0xffffffffu, l, 1);
            l += __shfl_xor_sync(0xffffffffu, l, 2);
            inv[half] = 1.f / l;
        }
        #pragma unroll
        for (int half = 0; half < 2; half++) {
            int i = i0 + w * 32 + mt * 16 + lr + half * 8;
            __nv_bfloat16* orow = out + ((size_t)(b * NPOS + i)) * C_ + h * DHEAD;
            #pragma unroll
            for (int nv = 0; nv < 4; nv++) {
                __nv_bfloat162 pr = __floats2bfloat162_rn(
                    oacc[mt][nv][half * 2 + 0] * inv[half],
                    oacc[mt][nv][half * 2 + 1] * inv[half]);
                *(__nv_bfloat162*)&orow[nv * 8 + lc] = pr;
            }
        }
    }
}

// ---------------------------------------------------------------------------
// Host launch
// ---------------------------------------------------------------------------
extern "C" void kernel_launch(void* const* d_in, const int* in_sizes, int n_in,
                              void* d_out, int out_size)
{
    const float* x       = (const float*)d_in[0];
    const float* qkv_w   = (const float*)d_in[1];
    const float* proj_w  = (const float*)d_in[2];
    const float* proj_b  = (const float*)d_in[3];
    const float* ffn_w1  = (const float*)d_in[4];
    const float* ffn_b1  = (const float*)d_in[5];
    const float* ffn_w2  = (const float*)d_in[6];
    const float* ffn_b2  = (const float*)d_in[7];
    const float* n1w     = (const float*)d_in[8];
    const float* n1b     = (const float*)d_in[9];
    const float* n2w     = (const float*)d_in[10];
    const float* n2b     = (const float*)d_in[11];
    const float* btab    = (const float*)d_in[12];
    const int*   ridx    = (const int*)d_in[13];
    float* out = (float*)d_out;

    float* scratch = nullptr;
    cudaGetSymbolAddress((void**)&scratch, g_scratch);

    __nv_bfloat16* wb    = (__nv_bfloat16*)(scratch + OFF_WB);
    __nv_bfloat16* x1b   = (__nv_bfloat16*)(scratch + OFF_X1B);
    __nv_bfloat16* qkvb  = (__nv_bfloat16*)(scratch + OFF_QKVB);
    __nv_bfloat16* bias9 = (__nv_bfloat16*)(scratch + OFF_BIAS8);
    __nv_bfloat16* attnb = (__nv_bfloat16*)(scratch + OFF_ATTNB);
    float*         x3    = scratch + OFF_X3;
    __nv_bfloat16* x4b   = (__nv_bfloat16*)(scratch + OFF_X4B);
    __nv_bfloat16* h1b   = (__nv_bfloat16*)(scratch + OFF_H1B);

    static bool attrSet = false;
    if (!attrSet) {
        cudaFuncSetAttribute(proj_ln_kernel,
                             cudaFuncAttributeMaxDynamicSharedMemorySize, PSMEM_BYTES);
        attrSet = true;
    }

    // 0. Merged prep: weight conversion + bias precompute + LN1
    prep_kernel<<<4608, 256>>>(qkv_w, proj_w, ffn_w1, ffn_w2, wb,
                               btab, ridx, bias9, x, n1w, n1b, x1b);

    // 1. QKV GEMM -> bf16 q/k/v head layout
    mma_gemm<0><<<dim3(768 / 128, NTOK / 128), 128>>>(
        x1b, wb + WB_QKV, NTOK, 768, C_, nullptr, nullptr, nullptr, qkvb);

    // 2. Flash attention (Q-tile 128, shared K/V fragments, quarter bias)
    attn_mma<<<dim3(NPOS / 128, HEADS, B_), 128>>>(qkvb, bias9, attnb);

    // 3. Fused proj GEMM + bias + residual(x) + LN2 -> x3 / x4b (64-row CTAs)
    proj_ln_kernel<<<NTOK / 64, 256, PSMEM_BYTES>>>(
        attnb, wb + WB_PROJ, proj_b, x, n2w, n2b, x3, x4b);

    // 4. FFN1 + GELU -> bf16 h1
    mma_gemm<2><<<dim3(HID / 128, NTOK / 128), 128>>>(
        x4b, wb + WB_W1, NTOK, HID, C_, ffn_b1, nullptr, nullptr, h1b);

    // 5. FFN2 + bias + residual(x3) -> fp32 output (B,C,H,W)
    mma_gemm<3><<<dim3(C_ / 128, NTOK / 128), 128>>>(
        h1b, wb + WB_W2, NTOK, C_, HID, ffn_b2, x3, out, nullptr);
}